// round 12
// baseline (speedup 1.0000x reference)
#include <cuda_runtime.h>
#include <math.h>

#define NI   3
#define NS   32
#define NC   512
#define HH   22
#define OH   23
#define NPIX (OH*OH)        // 529
#define HW   (HH*HH)        // 484
#define NE   (NI*NS)        // 96
#define TAPS 16
#define WSZ  (NS*NC*TAPS)   // 262144
#define CSPLIT 16
#define PH   27             // padded rm tile stride
#define SPP  4              // channel-pairs per conv stage
#define SROW 26             // conv smem tile rows
#define SST  28             // conv smem tile row stride (float2)
#define GFW  24             // grad feat smem row stride (float2): 22 + 2 zero pad
#define NPAIR (NC/2)        // 256 pairs per element

// ---------------- scratch (device globals; no runtime allocation) ----------------
__device__ __align__(16) float2 g_feat2[NE*NPAIR*HW];  // pair-interleaved feat (95MB)
__device__ float g_spart[CSPLIT*NE*NPIX]; // conv partials per channel-chunk
__device__ float g_label[NE*NPIX];
__device__ float g_scores[NE*NPIX];       // maintained scores (recurrence)
__device__ float g_sg[NE*NPIX];           // conv(feat, wg) summed
__device__ float g_rm[NE*NPIX];           // residuals_mapped
__device__ float g_w[WSZ];                // working weights
__device__ float g_wg[WSZ];               // weights_grad
__device__ float g_wgpart[NI*WSZ];        // per-image grad partials
__device__ float g_alpha_num[2][NS];      // parity double-buffered
__device__ float g_alpha_den[2][NS];
__device__ float g_loss_data[8];
__device__ float g_wsq[8];

// ---------------- helpers ----------------
__device__ __forceinline__ float2 f2fma(float2 a, float2 b, float2 c) {
    float2 d;
    asm("fma.rn.f32x2 %0, %1, %2, %3;"
        : "=l"(reinterpret_cast<unsigned long long&>(d))
        : "l"(reinterpret_cast<unsigned long long&>(a)),
          "l"(reinterpret_cast<unsigned long long&>(b)),
          "l"(reinterpret_cast<unsigned long long&>(c)));
    return d;
}

__device__ __forceinline__ void cpa16(void* dst, const void* src) {
    unsigned int d = (unsigned int)__cvta_generic_to_shared(dst);
    asm volatile("cp.async.cg.shared.global [%0], [%1], 16;" :: "r"(d), "l"(src));
}
__device__ __forceinline__ void cpa_commit() { asm volatile("cp.async.commit_group;"); }
template<int N> __device__ __forceinline__ void cpa_wait() {
    asm volatile("cp.async.wait_group %0;" :: "n"(N));
}

__device__ __forceinline__ float block_reduce_sum(float v, float* sbuf) {
    int lane = threadIdx.x & 31, wid = threadIdx.x >> 5;
    #pragma unroll
    for (int o = 16; o > 0; o >>= 1) v += __shfl_down_sync(0xffffffffu, v, o);
    if (lane == 0) sbuf[wid] = v;
    __syncthreads();
    int nw = (blockDim.x + 31) >> 5;
    v = (threadIdx.x < nw) ? sbuf[threadIdx.x] : 0.f;
    if (wid == 0) {
        #pragma unroll
        for (int o = 16; o > 0; o >>= 1) v += __shfl_down_sync(0xffffffffu, v, o);
    }
    return v;  // valid on thread 0
}

// ---------------- prep: repack feat into pair-interleaved float2 ----------------
__global__ void k_prep(const float* __restrict__ feat) {
    int idx = blockIdx.x * 256 + threadIdx.x;
    if (idx >= NE*NPAIR*HW) return;
    int p = idx / HW, q = idx - p*HW;          // p = global pair = e*256 + pr
    const float* src = feat + (size_t)(p*2)*HW + q;
    g_feat2[idx] = make_float2(src[0], src[HW]);
}

// ---------------- init: copy weights, build label, zero accumulators ----------------
__global__ void k_init(const float* __restrict__ w_in, const float* __restrict__ bb) {
    int idx = blockIdx.x * 256 + threadIdx.x;
    if (idx < WSZ) g_w[idx] = w_in[idx];
    if (idx < NE*NPIX) {
        int e = idx / NPIX, p = idx - e*NPIX;
        int y = p / OH, x = p - y*OH;
        const float* b = bb + e*4;
        float cc = (b[0] + 0.5f*b[2]) * 0.0625f;   // col center
        float cr = (b[1] + 0.5f*b[3]) * 0.0625f;   // row center
        float dy = (float)y - cr, dx = (float)x - cc;
        g_label[idx] = expf(-0.5f*dy*dy) * expf(-0.5f*dx*dx);
    }
    if (blockIdx.x == 0 && threadIdx.x < 8) {
        g_loss_data[threadIdx.x] = 0.f;
        g_wsq[threadIdx.x] = 0.f;
    }
    if (blockIdx.x == 1 && threadIdx.x < NS) {
        g_alpha_num[0][threadIdx.x] = 0.f;
        g_alpha_num[1][threadIdx.x] = 0.f;
        g_alpha_den[0][threadIdx.x] = 0.f;
        g_alpha_den[1][threadIdx.x] = 0.f;
    }
}

// ---------------- conv: one (e, 32-channel chunk) per block, cp.async double-buffered ----------------
// 96 threads = 24 output tiles (4x across, 6y down; tile 6w x 4t) x 4 pair-lanes. (R4-proven)
__global__ __launch_bounds__(96, 4) void k_conv(int use_wg) {
    __shared__ __align__(16) float2 sf[2][SPP*SROW*SST]; // 2 x 4 pairs x 26x28 = 46.6KB
    __shared__ float2 swt[16][TAPS];                     // 16 pairs x 16 taps
    const float* wts = use_wg ? g_wg : g_w;

    int b = blockIdx.x;
    int e = b % NE;              // i*NS + s
    int chunk = b / NE;          // 0..15
    int s = e % NS;
    int tid = threadIdx.x;
    int pl = tid & 3;            // pair lane within stage
    int t  = tid >> 2;           // tile 0..23
    int tx = t & 3, ty = t >> 2;
    int x0 = tx * 6, y0 = ty * 4;
    int sulim = (ty == 5) ? 6 : 7;   // skip dead row read at bottom tile

    for (int k = tid; k < 2*SPP*SROW*SST; k += 96)
        ((float2*)sf)[k] = make_float2(0.f, 0.f);
    for (int k = tid; k < 256; k += 96) {
        int pr = k >> 4, tap = k & 15;
        const float* wp = wts + (s*NC + chunk*32 + pr*2)*TAPS + tap;
        swt[pr][tap] = make_float2(wp[0], wp[TAPS]);
    }
    __syncthreads();

    const float2* fbase = g_feat2 + (size_t)(e*NPAIR + chunk*16)*HW;

    auto load_stage = [&](int st, float2* dstb) {
        for (int k = tid; k < 968; k += 96) {
            int p = k / 242, rem = k - p*242;
            int u = rem / 11, cc = rem - u*11;
            float2* dst = dstb + p*(SROW*SST) + (u+2)*SST + 2 + cc*2;
            const float2* src = fbase + (st*SPP + p)*HW + u*HH + cc*2;
            cpa16(dst, src);
        }
        cpa_commit();
    };

    float2 acc[4][6];
    #pragma unroll
    for (int r = 0; r < 4; r++)
        #pragma unroll
        for (int j = 0; j < 6; j++) acc[r][j] = make_float2(0.f, 0.f);

    load_stage(0, sf[0]);

    #pragma unroll 1
    for (int st = 0; st < 4; st++) {
        if (st < 3) { load_stage(st+1, sf[(st+1)&1]); cpa_wait<1>(); }
        else        { cpa_wait<0>(); }
        __syncthreads();

        const float2* sfp = sf[st&1] + pl*(SROW*SST);
        float2 wr[16];
        #pragma unroll
        for (int k = 0; k < 16; k++) wr[k] = swt[st*SPP + pl][k];

        #pragma unroll
        for (int su = 0; su < 7; su++) {
            if (su >= sulim) continue;
            const float2* fr = sfp + (y0+su)*SST + x0;
            float2 f[9];
            #pragma unroll
            for (int j = 0; j < 9; j++) f[j] = fr[j];
            #pragma unroll
            for (int ky = 0; ky < 4; ky++) {
                int r = su - ky;
                if (r < 0 || r > 3) continue;
                #pragma unroll
                for (int kx = 0; kx < 4; kx++) {
                    float2 w2 = wr[ky*4 + kx];
                    #pragma unroll
                    for (int j = 0; j < 6; j++)
                        acc[r][j] = f2fma(f[j+kx], w2, acc[r][j]);
                }
            }
        }
        __syncthreads();
    }

    float* op = g_spart + ((size_t)chunk*NE + e)*NPIX;
    #pragma unroll
    for (int r = 0; r < 4; r++) {
        #pragma unroll
        for (int j = 0; j < 6; j++) {
            float v = acc[r][j].x + acc[r][j].y;
            v += __shfl_down_sync(0xffffffffu, v, 1);
            v += __shfl_down_sync(0xffffffffu, v, 2);
            if (pl == 0) {
                int yy = y0 + r, xx = x0 + j;
                if (yy < OH && xx < OH) op[yy*OH + xx] = v;
            }
        }
    }
}

// ---------------- resid0: sum conv partials -> scores_0, rm_0, loss_data[0] ----------------
__global__ void k_resid0() {
    __shared__ float sred[32];
    int idx = blockIdx.x * 256 + threadIdx.x;
    float term = 0.f;
    if (idx < NE*NPIX) {
        float ssum = 0.f;
        #pragma unroll
        for (int ch = 0; ch < CSPLIT; ch++) ssum += g_spart[ch*(NE*NPIX) + idx];
        g_scores[idx] = ssum;
        float d = ssum - g_label[idx];
        g_rm[idx] = d * (1.f/3.f);
        term = d * d * (1.f/3.f);
    }
    float tot = block_reduce_sum(term, sred);
    if (threadIdx.x == 0) atomicAdd(&g_loss_data[0], tot);
}

// ---------------- grad: per-image partial of corr(feat, rm) ----------------
// rm stored PRE-DUPLICATED as float2 -> every rm operand is one LDS.64, no packing MOVs.
__global__ __launch_bounds__(128, 6) void k_grad() {
    __shared__ __align__(16) float2 gf[4*HH*GFW];       // 16.9KB
    __shared__ __align__(16) float2 srm2[PH*PH];        // duplicated rm, 5.8KB
    float* scr = (float*)gf;                            // 128x33 scratch alias

    int b = blockIdx.x;
    int i = b / (NS*16);
    int rem = b - i*(NS*16);
    int s = rem >> 4;
    int cg = rem & 15;
    int tid = threadIdx.x;
    int lane = tid & 31;
    int vseg = tid & 3;
    int uq   = (tid >> 2) & 7;
    int pr   = tid >> 5;
    int v0 = vseg * 6;
    int u0   = (uq < 6) ? uq*3 : 18 + (uq-6)*2;
    int ulen = (uq < 6) ? 3 : 2;

    for (int k = tid; k < 4*HH*GFW; k += 128) gf[k] = make_float2(0.f, 0.f);
    for (int k = tid; k < PH*PH; k += 128) srm2[k] = make_float2(0.f, 0.f);
    __syncthreads();
    for (int k = tid; k < NPIX; k += 128) {
        int y = k / OH, x = k - y*OH;
        float v = g_rm[(i*NS + s)*NPIX + k];
        srm2[(y+2)*PH + (x+2)] = make_float2(v, v);
    }

    const float2* fbase = g_feat2 + (size_t)((i*NS + s)*NPAIR + cg*16)*HW;

    #pragma unroll 1
    for (int st = 0; st < 4; st++) {
        __syncthreads();
        for (int k = tid; k < 968; k += 128) {
            int p = k / 242, r2 = k - p*242;
            int u = r2 / 11, cc = r2 - u*11;
            const float4* src = (const float4*)(fbase + (st*4 + p)*HW + u*HH) + cc;
            float4* dst = (float4*)(gf + p*(HH*GFW) + u*GFW) + cc;
            *dst = *src;
        }
        for (int k = tid; k < 176; k += 128) {
            int p = k / 44, r2 = k - p*44;
            int u = r2 >> 1, c = HH + (r2 & 1);
            gf[p*(HH*GFW) + u*GFW + c] = make_float2(0.f, 0.f);
        }
        __syncthreads();

        float2 acc[16];
        #pragma unroll
        for (int k = 0; k < 16; k++) acc[k] = make_float2(0.f, 0.f);

        const float2* fch = gf + pr*(HH*GFW);
        #pragma unroll 1
        for (int uu = 0; uu < ulen; uu++) {
            int u = u0 + uu;
            const float2* r0p = srm2 + (u+4)*PH + v0;      // ky=0
            const float2* r1p = r0p - PH;
            const float2* r2p = r1p - PH;
            const float2* r3p = r2p - PH;
            float2 w00=r0p[1], w01=r0p[2], w02=r0p[3];
            float2 w10=r1p[1], w11=r1p[2], w12=r1p[3];
            float2 w20=r2p[1], w21=r2p[2], w22=r2p[3];
            float2 w30=r3p[1], w31=r3p[2], w32=r3p[3];
            const float2* fr = fch + u*GFW + v0;
            #pragma unroll
            for (int v = 0; v < 6; v++) {
                float2 f = fr[v];
                float2 rn0 = r0p[v+4];
                acc[3]  = f2fma(f, w00, acc[3]);
                acc[2]  = f2fma(f, w01, acc[2]);
                acc[1]  = f2fma(f, w02, acc[1]);
                acc[0]  = f2fma(f, rn0, acc[0]);
                w00=w01; w01=w02; w02=rn0;
                float2 rn1 = r1p[v+4];
                acc[7]  = f2fma(f, w10, acc[7]);
                acc[6]  = f2fma(f, w11, acc[6]);
                acc[5]  = f2fma(f, w12, acc[5]);
                acc[4]  = f2fma(f, rn1, acc[4]);
                w10=w11; w11=w12; w12=rn1;
                float2 rn2 = r2p[v+4];
                acc[11] = f2fma(f, w20, acc[11]);
                acc[10] = f2fma(f, w21, acc[10]);
                acc[9]  = f2fma(f, w22, acc[9]);
                acc[8]  = f2fma(f, rn2, acc[8]);
                w20=w21; w21=w22; w22=rn2;
                float2 rn3 = r3p[v+4];
                acc[15] = f2fma(f, w30, acc[15]);
                acc[14] = f2fma(f, w31, acc[14]);
                acc[13] = f2fma(f, w32, acc[13]);
                acc[12] = f2fma(f, rn3, acc[12]);
                w30=w31; w31=w32; w32=rn3;
            }
        }

        __syncthreads();
        #pragma unroll
        for (int k = 0; k < 16; k++) {
            scr[(pr*32 + k)*33 + lane]      = acc[k].x;
            scr[(pr*32 + 16 + k)*33 + lane] = acc[k].y;
        }
        __syncthreads();
        {
            float sum = 0.f;
            #pragma unroll
            for (int p = 0; p < 32; p++) sum += scr[tid*33 + p];
            int pro = tid >> 5, half = (tid >> 4) & 1, tap = tid & 15;
            int c = cg*32 + (st*4 + pro)*2 + half;
            g_wgpart[(size_t)i*WSZ + (s*NC + c)*TAPS + tap] = sum;
        }
    }
}

// ---------------- combine grad partials: wg = sum_i part + reg*w; alpha_num; wsq ----------------
__global__ void k_comb(const float* __restrict__ freg, int t) {
    __shared__ float sred[32];
    int idx = blockIdx.x * 256 + threadIdx.x;   // grid covers exactly WSZ
    int s = idx >> 13;                          // / 8192
    float fr0 = freg[0];
    float regv = fmaxf(fr0*fr0, 1e-6f);
    float w = g_w[idx];
    float wg = g_wgpart[idx] + g_wgpart[WSZ + idx] + g_wgpart[2*WSZ + idx] + regv*w;
    g_wg[idx] = wg;
    float tn = block_reduce_sum(wg*wg, sred);
    if (threadIdx.x == 0) atomicAdd(&g_alpha_num[t&1][s], tn);
    __syncthreads();
    float tw = block_reduce_sum(w*w, sred);
    if (threadIdx.x == 0) atomicAdd(&g_wsq[t], tw);
}

// ---------------- alpha_den: (1/3)*sum conv(feat,wg)^2 ; also materialize g_sg ----------------
__global__ void k_den(int t) {
    __shared__ float sred[32];
    int e = blockIdx.x;
    int s = e % NS;
    float sum = 0.f;
    for (int p = threadIdx.x; p < NPIX; p += 256) {
        float v = 0.f;
        #pragma unroll
        for (int ch = 0; ch < CSPLIT; ch++) v += g_spart[ch*(NE*NPIX) + e*NPIX + p];
        g_sg[e*NPIX + p] = v;
        sum += v*v;
    }
    float tot = block_reduce_sum(sum, sred);
    if (threadIdx.x == 0) atomicAdd(&g_alpha_den[t&1][s], tot * (1.f/3.f));
}

// ---------------- merged update: weights, scores, rm_{t+1}, loss_data[t+1], zero next alphas ----------------
__global__ void k_upd(const float* __restrict__ lsl, const float* __restrict__ freg, int t) {
    __shared__ float sred[32];
    int idx = blockIdx.x * 256 + threadIdx.x;
    float fr0 = freg[0];
    float regv = fmaxf(fr0*fr0, 1e-6f);
    float step = expf(lsl[0]);
    int par = t & 1;
    if (idx < WSZ) {
        int s = idx >> 13;
        float num = g_alpha_num[par][s];
        float den = fmaxf(g_alpha_den[par][s] + regv*num, 1e-8f);
        g_w[idx] -= step * (num/den) * g_wg[idx];
        if (blockIdx.x == 0 && threadIdx.x < NS) {   // zero next-iteration slot
            g_alpha_num[par^1][threadIdx.x] = 0.f;
            g_alpha_den[par^1][threadIdx.x] = 0.f;
        }
    } else {
        int j = idx - WSZ;
        float term = 0.f;
        if (j < NE*NPIX) {
            int s = (j / NPIX) % NS;
            float num = g_alpha_num[par][s];
            float den = fmaxf(g_alpha_den[par][s] + regv*num, 1e-8f);
            float sc = g_scores[j] - step * (num/den) * g_sg[j];
            g_scores[j] = sc;
            float d = sc - g_label[j];
            g_rm[j] = d * (1.f/3.f);
            term = d * d * (1.f/3.f);
        }
        float tot = block_reduce_sum(term, sred);
        if (threadIdx.x == 0) atomicAdd(&g_loss_data[t+1], tot);
    }
}

// ---------------- final: weight writeback + wsq[5] (loss_data[5] from last k_upd) ----------------
__global__ void k_final(float* __restrict__ out) {
    __shared__ float sred[32];
    int j = blockIdx.x * 256 + threadIdx.x;   // grid covers exactly WSZ
    float wv = g_w[j];
    out[j] = wv;
    float tot = block_reduce_sum(wv*wv, sred);
    if (threadIdx.x == 0) atomicAdd(&g_wsq[5], tot);
}

// ---------------- losses writeback ----------------
__global__ void k_last(float* __restrict__ out, const float* __restrict__ freg) {
    float fr0 = freg[0];
    float regv = fmaxf(fr0*fr0, 1e-6f);
    int t = threadIdx.x;
    if (t < 6) out[WSZ + t] = (g_loss_data[t] + regv * g_wsq[t]) * (1.f/(float)NS);
}

// ---------------- launcher ----------------
extern "C" void kernel_launch(void* const* d_in, const int* in_sizes, int n_in,
                              void* d_out, int out_size) {
    const float* w_in = (const float*)d_in[0];
    const float* feat = (const float*)d_in[1];
    const float* bb   = (const float*)d_in[2];
    const float* lsl  = (const float*)d_in[3];
    const float* freg = (const float*)d_in[4];
    float* out = (float*)d_out;
    (void)in_sizes; (void)n_in; (void)out_size;

    k_init<<<1024, 256>>>(w_in, bb);
    k_prep<<<(NE*NPAIR*HW + 255)/256, 256>>>(feat);
    k_conv<<<NE*CSPLIT, 96>>>(0);                           // scores_0 partials
    k_resid0<<<(NE*NPIX + 255)/256, 256>>>();               // scores_0, rm_0, loss_data[0]
    for (int t = 0; t < 5; t++) {
        k_grad<<<NI*NS*16, 128>>>();                        // per-image grad partials
        k_comb<<<WSZ/256, 256>>>(freg, t);                  // wg, alpha_num, wsq[t]
        k_conv<<<NE*CSPLIT, 96>>>(1);                       // sg partials from wg
        k_den<<<NE, 256>>>(t);                              // alpha_den + g_sg
        k_upd<<<(WSZ + NE*NPIX + 255)/256, 256>>>(lsl, freg, t); // w/scores/rm/loss
    }
    k_final<<<WSZ/256, 256>>>(out);                         // weights out + wsq[5]
    k_last<<<1, 32>>>(out, freg);                           // losses out
}

// round 13
// speedup vs baseline: 1.2207x; 1.2207x over previous
#include <cuda_runtime.h>
#include <math.h>

#define NI   3
#define NS   32
#define NC   512
#define HH   22
#define OH   23
#define NPIX (OH*OH)        // 529
#define HW   (HH*HH)        // 484
#define NE   (NI*NS)        // 96
#define TAPS 16
#define WSZ  (NS*NC*TAPS)   // 262144
#define CSPLIT 16
#define PH   27             // padded rm tile stride
#define SPP  4              // channel-pairs per conv stage
#define SROW 26             // conv smem tile rows
#define SST  28             // conv smem tile row stride (float2)
#define GFW  24             // grad feat smem row stride (float2): 22 + 2 zero pad
#define NPAIR (NC/2)        // 256 pairs per element

// ---------------- scratch (device globals; no runtime allocation) ----------------
__device__ __align__(16) float2 g_feat2[NE*NPAIR*HW];  // pair-interleaved feat (95MB)
__device__ float g_spart[CSPLIT*NE*NPIX]; // conv partials per channel-chunk
__device__ float g_label[NE*NPIX];
__device__ float g_scores[NE*NPIX];       // maintained scores (recurrence)
__device__ float g_sg[NE*NPIX];           // conv(feat, wg) summed
__device__ float g_rm[NE*NPIX];           // residuals_mapped
__device__ float g_w[WSZ];                // working weights
__device__ float g_wg[WSZ];               // weights_grad
__device__ float g_wgpart[NI*WSZ];        // per-image grad partials
__device__ float g_alpha_num[2][NS];      // parity double-buffered
__device__ float g_alpha_den[2][NS];
__device__ float g_loss_data[8];
__device__ float g_wsq[8];

// ---------------- helpers ----------------
__device__ __forceinline__ float2 f2fma(float2 a, float2 b, float2 c) {
    float2 d;
    asm("fma.rn.f32x2 %0, %1, %2, %3;"
        : "=l"(reinterpret_cast<unsigned long long&>(d))
        : "l"(reinterpret_cast<unsigned long long&>(a)),
          "l"(reinterpret_cast<unsigned long long&>(b)),
          "l"(reinterpret_cast<unsigned long long&>(c)));
    return d;
}
__device__ __forceinline__ float2 fdup(float v) { return make_float2(v, v); }

__device__ __forceinline__ void cpa16(void* dst, const void* src) {
    unsigned int d = (unsigned int)__cvta_generic_to_shared(dst);
    asm volatile("cp.async.cg.shared.global [%0], [%1], 16;" :: "r"(d), "l"(src));
}
__device__ __forceinline__ void cpa_commit() { asm volatile("cp.async.commit_group;"); }
template<int N> __device__ __forceinline__ void cpa_wait() {
    asm volatile("cp.async.wait_group %0;" :: "n"(N));
}

__device__ __forceinline__ float block_reduce_sum(float v, float* sbuf) {
    int lane = threadIdx.x & 31, wid = threadIdx.x >> 5;
    #pragma unroll
    for (int o = 16; o > 0; o >>= 1) v += __shfl_down_sync(0xffffffffu, v, o);
    if (lane == 0) sbuf[wid] = v;
    __syncthreads();
    int nw = (blockDim.x + 31) >> 5;
    v = (threadIdx.x < nw) ? sbuf[threadIdx.x] : 0.f;
    if (wid == 0) {
        #pragma unroll
        for (int o = 16; o > 0; o >>= 1) v += __shfl_down_sync(0xffffffffu, v, o);
    }
    return v;  // valid on thread 0
}

// ---------------- prep: repack feat into pair-interleaved float2 ----------------
__global__ void k_prep(const float* __restrict__ feat) {
    int idx = blockIdx.x * 256 + threadIdx.x;
    if (idx >= NE*NPAIR*HW) return;
    int p = idx / HW, q = idx - p*HW;          // p = global pair = e*256 + pr
    const float* src = feat + (size_t)(p*2)*HW + q;
    g_feat2[idx] = make_float2(src[0], src[HW]);
}

// ---------------- init: copy weights, build label, zero accumulators ----------------
__global__ void k_init(const float* __restrict__ w_in, const float* __restrict__ bb) {
    int idx = blockIdx.x * 256 + threadIdx.x;
    if (idx < WSZ) g_w[idx] = w_in[idx];
    if (idx < NE*NPIX) {
        int e = idx / NPIX, p = idx - e*NPIX;
        int y = p / OH, x = p - y*OH;
        const float* b = bb + e*4;
        float cc = (b[0] + 0.5f*b[2]) * 0.0625f;   // col center
        float cr = (b[1] + 0.5f*b[3]) * 0.0625f;   // row center
        float dy = (float)y - cr, dx = (float)x - cc;
        g_label[idx] = expf(-0.5f*dy*dy) * expf(-0.5f*dx*dx);
    }
    if (blockIdx.x == 0 && threadIdx.x < 8) {
        g_loss_data[threadIdx.x] = 0.f;
        g_wsq[threadIdx.x] = 0.f;
    }
    if (blockIdx.x == 1 && threadIdx.x < NS) {
        g_alpha_num[0][threadIdx.x] = 0.f;
        g_alpha_num[1][threadIdx.x] = 0.f;
        g_alpha_den[0][threadIdx.x] = 0.f;
        g_alpha_den[1][threadIdx.x] = 0.f;
    }
}

// ---------------- conv: one (e, 32-channel chunk) per block, cp.async double-buffered ----------------
// 96 threads = 24 output tiles (4x across, 6y down; tile 6w x 4t) x 4 pair-lanes. (R4-proven)
__global__ __launch_bounds__(96, 4) void k_conv(int use_wg) {
    __shared__ __align__(16) float2 sf[2][SPP*SROW*SST]; // 2 x 4 pairs x 26x28 = 46.6KB
    __shared__ float2 swt[16][TAPS];                     // 16 pairs x 16 taps
    const float* wts = use_wg ? g_wg : g_w;

    int b = blockIdx.x;
    int e = b % NE;              // i*NS + s
    int chunk = b / NE;          // 0..15
    int s = e % NS;
    int tid = threadIdx.x;
    int pl = tid & 3;            // pair lane within stage
    int t  = tid >> 2;           // tile 0..23
    int tx = t & 3, ty = t >> 2;
    int x0 = tx * 6, y0 = ty * 4;
    int sulim = (ty == 5) ? 6 : 7;   // skip dead row read at bottom tile

    for (int k = tid; k < 2*SPP*SROW*SST; k += 96)
        ((float2*)sf)[k] = make_float2(0.f, 0.f);
    for (int k = tid; k < 256; k += 96) {
        int pr = k >> 4, tap = k & 15;
        const float* wp = wts + (s*NC + chunk*32 + pr*2)*TAPS + tap;
        swt[pr][tap] = make_float2(wp[0], wp[TAPS]);
    }
    __syncthreads();

    const float2* fbase = g_feat2 + (size_t)(e*NPAIR + chunk*16)*HW;

    auto load_stage = [&](int st, float2* dstb) {
        for (int k = tid; k < 968; k += 96) {
            int p = k / 242, rem = k - p*242;
            int u = rem / 11, cc = rem - u*11;
            float2* dst = dstb + p*(SROW*SST) + (u+2)*SST + 2 + cc*2;
            const float2* src = fbase + (st*SPP + p)*HW + u*HH + cc*2;
            cpa16(dst, src);
        }
        cpa_commit();
    };

    float2 acc[4][6];
    #pragma unroll
    for (int r = 0; r < 4; r++)
        #pragma unroll
        for (int j = 0; j < 6; j++) acc[r][j] = make_float2(0.f, 0.f);

    load_stage(0, sf[0]);

    #pragma unroll 1
    for (int st = 0; st < 4; st++) {
        if (st < 3) { load_stage(st+1, sf[(st+1)&1]); cpa_wait<1>(); }
        else        { cpa_wait<0>(); }
        __syncthreads();

        const float2* sfp = sf[st&1] + pl*(SROW*SST);
        float2 wr[16];
        #pragma unroll
        for (int k = 0; k < 16; k++) wr[k] = swt[st*SPP + pl][k];

        #pragma unroll
        for (int su = 0; su < 7; su++) {
            if (su >= sulim) continue;
            const float2* fr = sfp + (y0+su)*SST + x0;
            float2 f[9];
            #pragma unroll
            for (int j = 0; j < 9; j++) f[j] = fr[j];
            #pragma unroll
            for (int ky = 0; ky < 4; ky++) {
                int r = su - ky;
                if (r < 0 || r > 3) continue;
                #pragma unroll
                for (int kx = 0; kx < 4; kx++) {
                    float2 w2 = wr[ky*4 + kx];
                    #pragma unroll
                    for (int j = 0; j < 6; j++)
                        acc[r][j] = f2fma(f[j+kx], w2, acc[r][j]);
                }
            }
        }
        __syncthreads();
    }

    float* op = g_spart + ((size_t)chunk*NE + e)*NPIX;
    #pragma unroll
    for (int r = 0; r < 4; r++) {
        #pragma unroll
        for (int j = 0; j < 6; j++) {
            float v = acc[r][j].x + acc[r][j].y;
            v += __shfl_down_sync(0xffffffffu, v, 1);
            v += __shfl_down_sync(0xffffffffu, v, 2);
            if (pl == 0) {
                int yy = y0 + r, xx = x0 + j;
                if (yy < OH && xx < OH) op[yy*OH + xx] = v;
            }
        }
    }
}

// ---------------- resid0: sum conv partials -> scores_0, rm_0, loss_data[0] ----------------
__global__ void k_resid0() {
    __shared__ float sred[32];
    int idx = blockIdx.x * 256 + threadIdx.x;
    float term = 0.f;
    if (idx < NE*NPIX) {
        float ssum = 0.f;
        #pragma unroll
        for (int ch = 0; ch < CSPLIT; ch++) ssum += g_spart[ch*(NE*NPIX) + idx];
        g_scores[idx] = ssum;
        float d = ssum - g_label[idx];
        g_rm[idx] = d * (1.f/3.f);
        term = d * d * (1.f/3.f);
    }
    float tot = block_reduce_sum(term, sred);
    if (threadIdx.x == 0) atomicAdd(&g_loss_data[0], tot);
}

// ---------------- grad: per-image partial of corr(feat, rm) (R11-proven layout) ----------------
// Stage feat loads now go global->shared via cp.async (no register round-trip).
__global__ __launch_bounds__(128, 7) void k_grad() {
    __shared__ __align__(16) float2 gf[4*HH*GFW];       // 16.9KB
    __shared__ float srm[PH*PH];
    float* scr = (float*)gf;                            // 128x33 scratch alias

    int b = blockIdx.x;
    int i = b / (NS*16);
    int rem = b - i*(NS*16);
    int s = rem >> 4;
    int cg = rem & 15;
    int tid = threadIdx.x;
    int lane = tid & 31;
    int vseg = tid & 3;
    int uq   = (tid >> 2) & 7;
    int pr   = tid >> 5;
    int v0 = vseg * 6;
    int u0   = (uq < 6) ? uq*3 : 18 + (uq-6)*2;
    int ulen = (uq < 6) ? 3 : 2;

    for (int k = tid; k < 4*HH*GFW; k += 128) gf[k] = make_float2(0.f, 0.f);
    for (int k = tid; k < PH*PH; k += 128) srm[k] = 0.f;
    __syncthreads();
    for (int k = tid; k < NPIX; k += 128) {
        int y = k / OH, x = k - y*OH;
        srm[(y+2)*PH + (x+2)] = g_rm[(i*NS + s)*NPIX + k];
    }

    const float2* fbase = g_feat2 + (size_t)((i*NS + s)*NPAIR + cg*16)*HW;

    #pragma unroll 1
    for (int st = 0; st < 4; st++) {
        __syncthreads();
        // feat stage load: 4 pairs x 22 rows x 11 x 16B via cp.async
        for (int k = tid; k < 968; k += 128) {
            int p = k / 242, r2 = k - p*242;
            int u = r2 / 11, cc = r2 - u*11;
            const float2* src = fbase + (st*4 + p)*HW + u*HH + cc*2;
            float2* dst = gf + p*(HH*GFW) + u*GFW + cc*2;
            cpa16(dst, src);
        }
        // re-zero right-pad cols (scratch reduction dirtied them last stage)
        for (int k = tid; k < 176; k += 128) {
            int p = k / 44, r2 = k - p*44;
            int u = r2 >> 1, c = HH + (r2 & 1);
            gf[p*(HH*GFW) + u*GFW + c] = make_float2(0.f, 0.f);
        }
        cpa_commit();
        cpa_wait<0>();
        __syncthreads();

        float2 acc[16];
        #pragma unroll
        for (int k = 0; k < 16; k++) acc[k] = make_float2(0.f, 0.f);

        const float2* fch = gf + pr*(HH*GFW);
        #pragma unroll 1
        for (int uu = 0; uu < ulen; uu++) {
            int u = u0 + uu;
            const float* r0p = srm + (u+4)*PH + v0;
            const float* r1p = r0p - PH;
            const float* r2p = r1p - PH;
            const float* r3p = r2p - PH;
            float w00=r0p[1], w01=r0p[2], w02=r0p[3];
            float w10=r1p[1], w11=r1p[2], w12=r1p[3];
            float w20=r2p[1], w21=r2p[2], w22=r2p[3];
            float w30=r3p[1], w31=r3p[2], w32=r3p[3];
            const float2* fr = fch + u*GFW + v0;
            #pragma unroll
            for (int v = 0; v < 6; v++) {
                float2 f = fr[v];
                float rn0 = r0p[v+4];
                acc[3]  = f2fma(f, fdup(w00), acc[3]);
                acc[2]  = f2fma(f, fdup(w01), acc[2]);
                acc[1]  = f2fma(f, fdup(w02), acc[1]);
                acc[0]  = f2fma(f, fdup(rn0), acc[0]);
                w00=w01; w01=w02; w02=rn0;
                float rn1 = r1p[v+4];
                acc[7]  = f2fma(f, fdup(w10), acc[7]);
                acc[6]  = f2fma(f, fdup(w11), acc[6]);
                acc[5]  = f2fma(f, fdup(w12), acc[5]);
                acc[4]  = f2fma(f, fdup(rn1), acc[4]);
                w10=w11; w11=w12; w12=rn1;
                float rn2 = r2p[v+4];
                acc[11] = f2fma(f, fdup(w20), acc[11]);
                acc[10] = f2fma(f, fdup(w21), acc[10]);
                acc[9]  = f2fma(f, fdup(w22), acc[9]);
                acc[8]  = f2fma(f, fdup(rn2), acc[8]);
                w20=w21; w21=w22; w22=rn2;
                float rn3 = r3p[v+4];
                acc[15] = f2fma(f, fdup(w30), acc[15]);
                acc[14] = f2fma(f, fdup(w31), acc[14]);
                acc[13] = f2fma(f, fdup(w32), acc[13]);
                acc[12] = f2fma(f, fdup(rn3), acc[12]);
                w30=w31; w31=w32; w32=rn3;
            }
        }

        __syncthreads();
        #pragma unroll
        for (int k = 0; k < 16; k++) {
            scr[(pr*32 + k)*33 + lane]      = acc[k].x;
            scr[(pr*32 + 16 + k)*33 + lane] = acc[k].y;
        }
        __syncthreads();
        {
            float sum = 0.f;
            #pragma unroll
            for (int p = 0; p < 32; p++) sum += scr[tid*33 + p];
            int pro = tid >> 5, half = (tid >> 4) & 1, tap = tid & 15;
            int c = cg*32 + (st*4 + pro)*2 + half;
            g_wgpart[(size_t)i*WSZ + (s*NC + c)*TAPS + tap] = sum;
        }
    }
}

// ---------------- combine grad partials: wg = sum_i part + reg*w; alpha_num; wsq ----------------
__global__ void k_comb(const float* __restrict__ freg, int t) {
    __shared__ float sred[32];
    int idx = blockIdx.x * 256 + threadIdx.x;   // grid covers exactly WSZ
    int s = idx >> 13;                          // / 8192
    float fr0 = freg[0];
    float regv = fmaxf(fr0*fr0, 1e-6f);
    float w = g_w[idx];
    float wg = g_wgpart[idx] + g_wgpart[WSZ + idx] + g_wgpart[2*WSZ + idx] + regv*w;
    g_wg[idx] = wg;
    float tn = block_reduce_sum(wg*wg, sred);
    if (threadIdx.x == 0) atomicAdd(&g_alpha_num[t&1][s], tn);
    __syncthreads();
    float tw = block_reduce_sum(w*w, sred);
    if (threadIdx.x == 0) atomicAdd(&g_wsq[t], tw);
}

// ---------------- alpha_den: (1/3)*sum conv(feat,wg)^2 ; also materialize g_sg ----------------
__global__ void k_den(int t) {
    __shared__ float sred[32];
    int e = blockIdx.x;
    int s = e % NS;
    float sum = 0.f;
    for (int p = threadIdx.x; p < NPIX; p += 256) {
        float v = 0.f;
        #pragma unroll
        for (int ch = 0; ch < CSPLIT; ch++) v += g_spart[ch*(NE*NPIX) + e*NPIX + p];
        g_sg[e*NPIX + p] = v;
        sum += v*v;
    }
    float tot = block_reduce_sum(sum, sred);
    if (threadIdx.x == 0) atomicAdd(&g_alpha_den[t&1][s], tot * (1.f/3.f));
}

// ---------------- merged update: weights, scores, rm_{t+1}, loss_data[t+1], zero next alphas ----------------
__global__ void k_upd(const float* __restrict__ lsl, const float* __restrict__ freg, int t) {
    __shared__ float sred[32];
    int idx = blockIdx.x * 256 + threadIdx.x;
    float fr0 = freg[0];
    float regv = fmaxf(fr0*fr0, 1e-6f);
    float step = expf(lsl[0]);
    int par = t & 1;
    if (idx < WSZ) {
        int s = idx >> 13;
        float num = g_alpha_num[par][s];
        float den = fmaxf(g_alpha_den[par][s] + regv*num, 1e-8f);
        g_w[idx] -= step * (num/den) * g_wg[idx];
        if (blockIdx.x == 0 && threadIdx.x < NS) {   // zero next-iteration slot
            g_alpha_num[par^1][threadIdx.x] = 0.f;
            g_alpha_den[par^1][threadIdx.x] = 0.f;
        }
    } else {
        int j = idx - WSZ;
        float term = 0.f;
        if (j < NE*NPIX) {
            int s = (j / NPIX) % NS;
            float num = g_alpha_num[par][s];
            float den = fmaxf(g_alpha_den[par][s] + regv*num, 1e-8f);
            float sc = g_scores[j] - step * (num/den) * g_sg[j];
            g_scores[j] = sc;
            float d = sc - g_label[j];
            g_rm[j] = d * (1.f/3.f);
            term = d * d * (1.f/3.f);
        }
        float tot = block_reduce_sum(term, sred);
        if (threadIdx.x == 0) atomicAdd(&g_loss_data[t+1], tot);
    }
}

// ---------------- final: weight writeback + wsq[5] (loss_data[5] from last k_upd) ----------------
__global__ void k_final(float* __restrict__ out) {
    __shared__ float sred[32];
    int j = blockIdx.x * 256 + threadIdx.x;   // grid covers exactly WSZ
    float wv = g_w[j];
    out[j] = wv;
    float tot = block_reduce_sum(wv*wv, sred);
    if (threadIdx.x == 0) atomicAdd(&g_wsq[5], tot);
}

// ---------------- losses writeback ----------------
__global__ void k_last(float* __restrict__ out, const float* __restrict__ freg) {
    float fr0 = freg[0];
    float regv = fmaxf(fr0*fr0, 1e-6f);
    int t = threadIdx.x;
    if (t < 6) out[WSZ + t] = (g_loss_data[t] + regv * g_wsq[t]) * (1.f/(float)NS);
}

// ---------------- launcher ----------------
extern "C" void kernel_launch(void* const* d_in, const int* in_sizes, int n_in,
                              void* d_out, int out_size) {
    const float* w_in = (const float*)d_in[0];
    const float* feat = (const float*)d_in[1];
    const float* bb   = (const float*)d_in[2];
    const float* lsl  = (const float*)d_in[3];
    const float* freg = (const float*)d_in[4];
    float* out = (float*)d_out;
    (void)in_sizes; (void)n_in; (void)out_size;

    k_init<<<1024, 256>>>(w_in, bb);
    k_prep<<<(NE*NPAIR*HW + 255)/256, 256>>>(feat);
    k_conv<<<NE*CSPLIT, 96>>>(0);                           // scores_0 partials
    k_resid0<<<(NE*NPIX + 255)/256, 256>>>();               // scores_0, rm_0, loss_data[0]
    for (int t = 0; t < 5; t++) {
        k_grad<<<NI*NS*16, 128>>>();                        // per-image grad partials
        k_comb<<<WSZ/256, 256>>>(freg, t);                  // wg, alpha_num, wsq[t]
        k_conv<<<NE*CSPLIT, 96>>>(1);                       // sg partials from wg
        k_den<<<NE, 256>>>(t);                              // alpha_den + g_sg
        k_upd<<<(WSZ + NE*NPIX + 255)/256, 256>>>(lsl, freg, t); // w/scores/rm/loss
    }
    k_final<<<WSZ/256, 256>>>(out);                         // weights out + wsq[5]
    k_last<<<1, 32>>>(out, freg);                           // losses out
}

// round 14
// speedup vs baseline: 1.2239x; 1.0026x over previous
#include <cuda_runtime.h>
#include <math.h>

#define NI   3
#define NS   32
#define NC   512
#define HH   22
#define OH   23
#define NPIX (OH*OH)        // 529
#define HW   (HH*HH)        // 484
#define NE   (NI*NS)        // 96
#define TAPS 16
#define WSZ  (NS*NC*TAPS)   // 262144
#define CSPLIT 16
#define PH   27             // padded rm tile stride
#define SPP  4              // channel-pairs per conv stage
#define SROW 26             // conv smem tile rows
#define SST  28             // conv smem tile row stride (float2)
#define GFW  24             // grad feat smem row stride (float2): 22 + 2 zero pad
#define NPAIR (NC/2)        // 256 pairs per element

// ---------------- scratch (device globals; no runtime allocation) ----------------
__device__ __align__(16) float2 g_feat2[NE*NPAIR*HW];  // pair-interleaved feat (95MB)
__device__ float g_spart[CSPLIT*NE*NPIX]; // conv partials per channel-chunk
__device__ float g_label[NE*NPIX];
__device__ float g_scores[NE*NPIX];       // maintained scores (recurrence)
__device__ float g_sg[NE*NPIX];           // conv(feat, wg) summed
__device__ float g_rm[NE*NPIX];           // residuals_mapped
__device__ float g_w[WSZ];                // working weights
__device__ float g_wg[WSZ];               // weights_grad
__device__ float g_wgpart[NI*WSZ];        // per-image grad partials
__device__ float g_alpha_num[2][NS];      // parity double-buffered
__device__ float g_alpha_den[2][NS];
__device__ float g_loss_data[8];
__device__ float g_wsq[8];

// ---------------- helpers ----------------
__device__ __forceinline__ float2 f2fma(float2 a, float2 b, float2 c) {
    float2 d;
    asm("fma.rn.f32x2 %0, %1, %2, %3;"
        : "=l"(reinterpret_cast<unsigned long long&>(d))
        : "l"(reinterpret_cast<unsigned long long&>(a)),
          "l"(reinterpret_cast<unsigned long long&>(b)),
          "l"(reinterpret_cast<unsigned long long&>(c)));
    return d;
}
__device__ __forceinline__ float2 fdup(float v) { return make_float2(v, v); }

__device__ __forceinline__ unsigned long long mkpol_evict_last() {
    unsigned long long pol;
    asm("createpolicy.fractional.L2::evict_last.b64 %0, 1.0;" : "=l"(pol));
    return pol;
}
// feat loads: cp.async with L2 evict_last hint (feat is meant to stay L2-resident)
__device__ __forceinline__ void cpa16p(void* dst, const void* src, unsigned long long pol) {
    unsigned int d = (unsigned int)__cvta_generic_to_shared(dst);
    asm volatile("cp.async.cg.shared.global.L2::cache_hint [%0], [%1], 16, %2;"
                 :: "r"(d), "l"(src), "l"(pol));
}
__device__ __forceinline__ void cpa_commit() { asm volatile("cp.async.commit_group;"); }
template<int N> __device__ __forceinline__ void cpa_wait() {
    asm volatile("cp.async.wait_group %0;" :: "n"(N));
}

__device__ __forceinline__ float block_reduce_sum(float v, float* sbuf) {
    int lane = threadIdx.x & 31, wid = threadIdx.x >> 5;
    #pragma unroll
    for (int o = 16; o > 0; o >>= 1) v += __shfl_down_sync(0xffffffffu, v, o);
    if (lane == 0) sbuf[wid] = v;
    __syncthreads();
    int nw = (blockDim.x + 31) >> 5;
    v = (threadIdx.x < nw) ? sbuf[threadIdx.x] : 0.f;
    if (wid == 0) {
        #pragma unroll
        for (int o = 16; o > 0; o >>= 1) v += __shfl_down_sync(0xffffffffu, v, o);
    }
    return v;  // valid on thread 0
}

// ---------------- prep: repack feat into pair-interleaved float2 ----------------
__global__ void k_prep(const float* __restrict__ feat) {
    int idx = blockIdx.x * 256 + threadIdx.x;
    if (idx >= NE*NPAIR*HW) return;
    int p = idx / HW, q = idx - p*HW;          // p = global pair = e*256 + pr
    const float* src = feat + (size_t)(p*2)*HW + q;
    g_feat2[idx] = make_float2(src[0], src[HW]);
}

// ---------------- init: copy weights, build label, zero accumulators ----------------
__global__ void k_init(const float* __restrict__ w_in, const float* __restrict__ bb) {
    int idx = blockIdx.x * 256 + threadIdx.x;
    if (idx < WSZ) g_w[idx] = w_in[idx];
    if (idx < NE*NPIX) {
        int e = idx / NPIX, p = idx - e*NPIX;
        int y = p / OH, x = p - y*OH;
        const float* b = bb + e*4;
        float cc = (b[0] + 0.5f*b[2]) * 0.0625f;   // col center
        float cr = (b[1] + 0.5f*b[3]) * 0.0625f;   // row center
        float dy = (float)y - cr, dx = (float)x - cc;
        g_label[idx] = expf(-0.5f*dy*dy) * expf(-0.5f*dx*dx);
    }
    if (blockIdx.x == 0 && threadIdx.x < 8) {
        g_loss_data[threadIdx.x] = 0.f;
        g_wsq[threadIdx.x] = 0.f;
    }
    if (blockIdx.x == 1 && threadIdx.x < NS) {
        g_alpha_num[0][threadIdx.x] = 0.f;
        g_alpha_num[1][threadIdx.x] = 0.f;
        g_alpha_den[0][threadIdx.x] = 0.f;
        g_alpha_den[1][threadIdx.x] = 0.f;
    }
}

// ---------------- conv: one (e, 32-channel chunk) per block, cp.async double-buffered ----------------
// 96 threads = 24 output tiles (4x across, 6y down; tile 6w x 4t) x 4 pair-lanes. (R4-proven)
__global__ __launch_bounds__(96, 4) void k_conv(int use_wg) {
    __shared__ __align__(16) float2 sf[2][SPP*SROW*SST]; // 2 x 4 pairs x 26x28 = 46.6KB
    __shared__ float2 swt[16][TAPS];                     // 16 pairs x 16 taps
    const float* wts = use_wg ? g_wg : g_w;

    int b = blockIdx.x;
    int e = b % NE;              // i*NS + s
    int chunk = b / NE;          // 0..15
    int s = e % NS;
    int tid = threadIdx.x;
    int pl = tid & 3;            // pair lane within stage
    int t  = tid >> 2;           // tile 0..23
    int tx = t & 3, ty = t >> 2;
    int x0 = tx * 6, y0 = ty * 4;
    int sulim = (ty == 5) ? 6 : 7;   // skip dead row read at bottom tile

    for (int k = tid; k < 2*SPP*SROW*SST; k += 96)
        ((float2*)sf)[k] = make_float2(0.f, 0.f);
    for (int k = tid; k < 256; k += 96) {
        int pr = k >> 4, tap = k & 15;
        const float* wp = wts + (s*NC + chunk*32 + pr*2)*TAPS + tap;
        swt[pr][tap] = make_float2(wp[0], wp[TAPS]);
    }
    __syncthreads();

    const float2* fbase = g_feat2 + (size_t)(e*NPAIR + chunk*16)*HW;
    unsigned long long pol = mkpol_evict_last();

    auto load_stage = [&](int st, float2* dstb) {
        for (int k = tid; k < 968; k += 96) {
            int p = k / 242, rem = k - p*242;
            int u = rem / 11, cc = rem - u*11;
            float2* dst = dstb + p*(SROW*SST) + (u+2)*SST + 2 + cc*2;
            const float2* src = fbase + (st*SPP + p)*HW + u*HH + cc*2;
            cpa16p(dst, src, pol);
        }
        cpa_commit();
    };

    float2 acc[4][6];
    #pragma unroll
    for (int r = 0; r < 4; r++)
        #pragma unroll
        for (int j = 0; j < 6; j++) acc[r][j] = make_float2(0.f, 0.f);

    load_stage(0, sf[0]);

    #pragma unroll 1
    for (int st = 0; st < 4; st++) {
        if (st < 3) { load_stage(st+1, sf[(st+1)&1]); cpa_wait<1>(); }
        else        { cpa_wait<0>(); }
        __syncthreads();

        const float2* sfp = sf[st&1] + pl*(SROW*SST);
        float2 wr[16];
        #pragma unroll
        for (int k = 0; k < 16; k++) wr[k] = swt[st*SPP + pl][k];

        #pragma unroll
        for (int su = 0; su < 7; su++) {
            if (su >= sulim) continue;
            const float2* fr = sfp + (y0+su)*SST + x0;
            float2 f[9];
            #pragma unroll
            for (int j = 0; j < 9; j++) f[j] = fr[j];
            #pragma unroll
            for (int ky = 0; ky < 4; ky++) {
                int r = su - ky;
                if (r < 0 || r > 3) continue;
                #pragma unroll
                for (int kx = 0; kx < 4; kx++) {
                    float2 w2 = wr[ky*4 + kx];
                    #pragma unroll
                    for (int j = 0; j < 6; j++)
                        acc[r][j] = f2fma(f[j+kx], w2, acc[r][j]);
                }
            }
        }
        __syncthreads();
    }

    float* op = g_spart + ((size_t)chunk*NE + e)*NPIX;
    #pragma unroll
    for (int r = 0; r < 4; r++) {
        #pragma unroll
        for (int j = 0; j < 6; j++) {
            float v = acc[r][j].x + acc[r][j].y;
            v += __shfl_down_sync(0xffffffffu, v, 1);
            v += __shfl_down_sync(0xffffffffu, v, 2);
            if (pl == 0) {
                int yy = y0 + r, xx = x0 + j;
                if (yy < OH && xx < OH) op[yy*OH + xx] = v;
            }
        }
    }
}

// ---------------- resid0: sum conv partials -> scores_0, rm_0, loss_data[0] ----------------
__global__ void k_resid0() {
    __shared__ float sred[32];
    int idx = blockIdx.x * 256 + threadIdx.x;
    float term = 0.f;
    if (idx < NE*NPIX) {
        float ssum = 0.f;
        #pragma unroll
        for (int ch = 0; ch < CSPLIT; ch++) ssum += g_spart[ch*(NE*NPIX) + idx];
        g_scores[idx] = ssum;
        float d = ssum - g_label[idx];
        g_rm[idx] = d * (1.f/3.f);
        term = d * d * (1.f/3.f);
    }
    float tot = block_reduce_sum(term, sred);
    if (threadIdx.x == 0) atomicAdd(&g_loss_data[0], tot);
}

// ---------------- grad: per-image partial of corr(feat, rm) (R13-proven) ----------------
__global__ __launch_bounds__(128, 7) void k_grad() {
    __shared__ __align__(16) float2 gf[4*HH*GFW];       // 16.9KB
    __shared__ float srm[PH*PH];
    float* scr = (float*)gf;                            // 128x33 scratch alias

    int b = blockIdx.x;
    int i = b / (NS*16);
    int rem = b - i*(NS*16);
    int s = rem >> 4;
    int cg = rem & 15;
    int tid = threadIdx.x;
    int lane = tid & 31;
    int vseg = tid & 3;
    int uq   = (tid >> 2) & 7;
    int pr   = tid >> 5;
    int v0 = vseg * 6;
    int u0   = (uq < 6) ? uq*3 : 18 + (uq-6)*2;
    int ulen = (uq < 6) ? 3 : 2;

    for (int k = tid; k < 4*HH*GFW; k += 128) gf[k] = make_float2(0.f, 0.f);
    for (int k = tid; k < PH*PH; k += 128) srm[k] = 0.f;
    __syncthreads();
    for (int k = tid; k < NPIX; k += 128) {
        int y = k / OH, x = k - y*OH;
        srm[(y+2)*PH + (x+2)] = g_rm[(i*NS + s)*NPIX + k];
    }

    const float2* fbase = g_feat2 + (size_t)((i*NS + s)*NPAIR + cg*16)*HW;
    unsigned long long pol = mkpol_evict_last();

    #pragma unroll 1
    for (int st = 0; st < 4; st++) {
        __syncthreads();
        // feat stage load: 4 pairs x 22 rows x 11 x 16B via cp.async (evict_last)
        for (int k = tid; k < 968; k += 128) {
            int p = k / 242, r2 = k - p*242;
            int u = r2 / 11, cc = r2 - u*11;
            const float2* src = fbase + (st*4 + p)*HW + u*HH + cc*2;
            float2* dst = gf + p*(HH*GFW) + u*GFW + cc*2;
            cpa16p(dst, src, pol);
        }
        // re-zero right-pad cols (scratch reduction dirtied them last stage)
        for (int k = tid; k < 176; k += 128) {
            int p = k / 44, r2 = k - p*44;
            int u = r2 >> 1, c = HH + (r2 & 1);
            gf[p*(HH*GFW) + u*GFW + c] = make_float2(0.f, 0.f);
        }
        cpa_commit();
        cpa_wait<0>();
        __syncthreads();

        float2 acc[16];
        #pragma unroll
        for (int k = 0; k < 16; k++) acc[k] = make_float2(0.f, 0.f);

        const float2* fch = gf + pr*(HH*GFW);
        #pragma unroll 1
        for (int uu = 0; uu < ulen; uu++) {
            int u = u0 + uu;
            const float* r0p = srm + (u+4)*PH + v0;
            const float* r1p = r0p - PH;
            const float* r2p = r1p - PH;
            const float* r3p = r2p - PH;
            float w00=r0p[1], w01=r0p[2], w02=r0p[3];
            float w10=r1p[1], w11=r1p[2], w12=r1p[3];
            float w20=r2p[1], w21=r2p[2], w22=r2p[3];
            float w30=r3p[1], w31=r3p[2], w32=r3p[3];
            const float2* fr = fch + u*GFW + v0;
            #pragma unroll
            for (int v = 0; v < 6; v++) {
                float2 f = fr[v];
                float rn0 = r0p[v+4];
                acc[3]  = f2fma(f, fdup(w00), acc[3]);
                acc[2]  = f2fma(f, fdup(w01), acc[2]);
                acc[1]  = f2fma(f, fdup(w02), acc[1]);
                acc[0]  = f2fma(f, fdup(rn0), acc[0]);
                w00=w01; w01=w02; w02=rn0;
                float rn1 = r1p[v+4];
                acc[7]  = f2fma(f, fdup(w10), acc[7]);
                acc[6]  = f2fma(f, fdup(w11), acc[6]);
                acc[5]  = f2fma(f, fdup(w12), acc[5]);
                acc[4]  = f2fma(f, fdup(rn1), acc[4]);
                w10=w11; w11=w12; w12=rn1;
                float rn2 = r2p[v+4];
                acc[11] = f2fma(f, fdup(w20), acc[11]);
                acc[10] = f2fma(f, fdup(w21), acc[10]);
                acc[9]  = f2fma(f, fdup(w22), acc[9]);
                acc[8]  = f2fma(f, fdup(rn2), acc[8]);
                w20=w21; w21=w22; w22=rn2;
                float rn3 = r3p[v+4];
                acc[15] = f2fma(f, fdup(w30), acc[15]);
                acc[14] = f2fma(f, fdup(w31), acc[14]);
                acc[13] = f2fma(f, fdup(w32), acc[13]);
                acc[12] = f2fma(f, fdup(rn3), acc[12]);
                w30=w31; w31=w32; w32=rn3;
            }
        }

        __syncthreads();
        #pragma unroll
        for (int k = 0; k < 16; k++) {
            scr[(pr*32 + k)*33 + lane]      = acc[k].x;
            scr[(pr*32 + 16 + k)*33 + lane] = acc[k].y;
        }
        __syncthreads();
        {
            float sum = 0.f;
            #pragma unroll
            for (int p = 0; p < 32; p++) sum += scr[tid*33 + p];
            int pro = tid >> 5, half = (tid >> 4) & 1, tap = tid & 15;
            int c = cg*32 + (st*4 + pro)*2 + half;
            g_wgpart[(size_t)i*WSZ + (s*NC + c)*TAPS + tap] = sum;
        }
    }
}

// ---------------- combine grad partials: wg = sum_i part + reg*w; alpha_num; wsq ----------------
__global__ void k_comb(const float* __restrict__ freg, int t) {
    __shared__ float sred[32];
    int idx = blockIdx.x * 256 + threadIdx.x;   // grid covers exactly WSZ
    int s = idx >> 13;                          // / 8192
    float fr0 = freg[0];
    float regv = fmaxf(fr0*fr0, 1e-6f);
    float w = g_w[idx];
    float wg = g_wgpart[idx] + g_wgpart[WSZ + idx] + g_wgpart[2*WSZ + idx] + regv*w;
    g_wg[idx] = wg;
    float tn = block_reduce_sum(wg*wg, sred);
    if (threadIdx.x == 0) atomicAdd(&g_alpha_num[t&1][s], tn);
    __syncthreads();
    float tw = block_reduce_sum(w*w, sred);
    if (threadIdx.x == 0) atomicAdd(&g_wsq[t], tw);
}

// ---------------- alpha_den: (1/3)*sum conv(feat,wg)^2 ; also materialize g_sg ----------------
__global__ void k_den(int t) {
    __shared__ float sred[32];
    int e = blockIdx.x;
    int s = e % NS;
    float sum = 0.f;
    for (int p = threadIdx.x; p < NPIX; p += 256) {
        float v = 0.f;
        #pragma unroll
        for (int ch = 0; ch < CSPLIT; ch++) v += g_spart[ch*(NE*NPIX) + e*NPIX + p];
        g_sg[e*NPIX + p] = v;
        sum += v*v;
    }
    float tot = block_reduce_sum(sum, sred);
    if (threadIdx.x == 0) atomicAdd(&g_alpha_den[t&1][s], tot * (1.f/3.f));
}

// ---------------- merged update: weights, scores, rm_{t+1}, loss_data[t+1], zero next alphas ----------------
__global__ void k_upd(const float* __restrict__ lsl, const float* __restrict__ freg, int t) {
    __shared__ float sred[32];
    int idx = blockIdx.x * 256 + threadIdx.x;
    float fr0 = freg[0];
    float regv = fmaxf(fr0*fr0, 1e-6f);
    float step = expf(lsl[0]);
    int par = t & 1;
    if (idx < WSZ) {
        int s = idx >> 13;
        float num = g_alpha_num[par][s];
        float den = fmaxf(g_alpha_den[par][s] + regv*num, 1e-8f);
        g_w[idx] -= step * (num/den) * g_wg[idx];
        if (blockIdx.x == 0 && threadIdx.x < NS) {   // zero next-iteration slot
            g_alpha_num[par^1][threadIdx.x] = 0.f;
            g_alpha_den[par^1][threadIdx.x] = 0.f;
        }
    } else {
        int j = idx - WSZ;
        float term = 0.f;
        if (j < NE*NPIX) {
            int s = (j / NPIX) % NS;
            float num = g_alpha_num[par][s];
            float den = fmaxf(g_alpha_den[par][s] + regv*num, 1e-8f);
            float sc = g_scores[j] - step * (num/den) * g_sg[j];
            g_scores[j] = sc;
            float d = sc - g_label[j];
            g_rm[j] = d * (1.f/3.f);
            term = d * d * (1.f/3.f);
        }
        float tot = block_reduce_sum(term, sred);
        if (threadIdx.x == 0) atomicAdd(&g_loss_data[t+1], tot);
    }
}

// ---------------- final: weight writeback + wsq[5] (loss_data[5] from last k_upd) ----------------
__global__ void k_final(float* __restrict__ out) {
    __shared__ float sred[32];
    int j = blockIdx.x * 256 + threadIdx.x;   // grid covers exactly WSZ
    float wv = g_w[j];
    out[j] = wv;
    float tot = block_reduce_sum(wv*wv, sred);
    if (threadIdx.x == 0) atomicAdd(&g_wsq[5], tot);
}

// ---------------- losses writeback ----------------
__global__ void k_last(float* __restrict__ out, const float* __restrict__ freg) {
    float fr0 = freg[0];
    float regv = fmaxf(fr0*fr0, 1e-6f);
    int t = threadIdx.x;
    if (t < 6) out[WSZ + t] = (g_loss_data[t] + regv * g_wsq[t]) * (1.f/(float)NS);
}

// ---------------- launcher ----------------
extern "C" void kernel_launch(void* const* d_in, const int* in_sizes, int n_in,
                              void* d_out, int out_size) {
    const float* w_in = (const float*)d_in[0];
    const float* feat = (const float*)d_in[1];
    const float* bb   = (const float*)d_in[2];
    const float* lsl  = (const float*)d_in[3];
    const float* freg = (const float*)d_in[4];
    float* out = (float*)d_out;
    (void)in_sizes; (void)n_in; (void)out_size;

    k_init<<<1024, 256>>>(w_in, bb);
    k_prep<<<(NE*NPAIR*HW + 255)/256, 256>>>(feat);
    k_conv<<<NE*CSPLIT, 96>>>(0);                           // scores_0 partials
    k_resid0<<<(NE*NPIX + 255)/256, 256>>>();               // scores_0, rm_0, loss_data[0]
    for (int t = 0; t < 5; t++) {
        k_grad<<<NI*NS*16, 128>>>();                        // per-image grad partials
        k_comb<<<WSZ/256, 256>>>(freg, t);                  // wg, alpha_num, wsq[t]
        k_conv<<<NE*CSPLIT, 96>>>(1);                       // sg partials from wg
        k_den<<<NE, 256>>>(t);                              // alpha_den + g_sg
        k_upd<<<(WSZ + NE*NPIX + 255)/256, 256>>>(lsl, freg, t); // w/scores/rm/loss
    }
    k_final<<<WSZ/256, 256>>>(out);                         // weights out + wsq[5]
    k_last<<<1, 32>>>(out, freg);                           // losses out
}

// round 15
// speedup vs baseline: 1.2396x; 1.0129x over previous
#include <cuda_runtime.h>
#include <math.h>

#define NI   3
#define NS   32
#define NC   512
#define HH   22
#define OH   23
#define NPIX (OH*OH)        // 529
#define HW   (HH*HH)        // 484
#define NE   (NI*NS)        // 96
#define TAPS 16
#define WSZ  (NS*NC*TAPS)   // 262144
#define CSPLIT 16
#define PH   27             // padded rm tile stride
#define SPP  4              // channel-pairs per conv stage
#define SROW 26             // conv smem tile rows
#define SST  28             // conv smem tile row stride (float2)
#define GFW  24             // grad feat smem row stride (float2): 22 + 2 zero pad
#define NPAIR (NC/2)        // 256 pairs per element

// ---------------- scratch (device globals; no runtime allocation) ----------------
__device__ __align__(16) float2 g_feat2[NE*NPAIR*HW];  // pair-interleaved feat (95MB)
__device__ float g_spart[CSPLIT*NE*NPIX]; // conv partials per channel-chunk
__device__ float g_label[NE*NPIX];
__device__ float g_scores[NE*NPIX];       // maintained scores (recurrence)
__device__ float g_sg[NE*NPIX];           // conv(feat, wg) summed
__device__ float g_rm[NE*NPIX];           // residuals_mapped
__device__ float g_w[WSZ];                // working weights
__device__ float g_wg[WSZ];               // weights_grad
__device__ float g_wgpart[NI*WSZ];        // per-image grad partials
__device__ float g_alpha_num[2][NS];      // parity double-buffered
__device__ float g_alpha_den[2][NS];
__device__ float g_loss_data[8];
__device__ float g_wsq[8];

// ---------------- helpers ----------------
__device__ __forceinline__ float2 f2fma(float2 a, float2 b, float2 c) {
    float2 d;
    asm("fma.rn.f32x2 %0, %1, %2, %3;"
        : "=l"(reinterpret_cast<unsigned long long&>(d))
        : "l"(reinterpret_cast<unsigned long long&>(a)),
          "l"(reinterpret_cast<unsigned long long&>(b)),
          "l"(reinterpret_cast<unsigned long long&>(c)));
    return d;
}
__device__ __forceinline__ float2 fdup(float v) { return make_float2(v, v); }

__device__ __forceinline__ unsigned long long mkpol_evict_last() {
    unsigned long long pol;
    asm("createpolicy.fractional.L2::evict_last.b64 %0, 1.0;" : "=l"(pol));
    return pol;
}
// feat loads: cp.async with L2 evict_last hint
__device__ __forceinline__ void cpa16p(void* dst, const void* src, unsigned long long pol) {
    unsigned int d = (unsigned int)__cvta_generic_to_shared(dst);
    asm volatile("cp.async.cg.shared.global.L2::cache_hint [%0], [%1], 16, %2;"
                 :: "r"(d), "l"(src), "l"(pol));
}
__device__ __forceinline__ void cpa_commit() { asm volatile("cp.async.commit_group;"); }
template<int N> __device__ __forceinline__ void cpa_wait() {
    asm volatile("cp.async.wait_group %0;" :: "n"(N));
}

__device__ __forceinline__ float block_reduce_sum(float v, float* sbuf) {
    int lane = threadIdx.x & 31, wid = threadIdx.x >> 5;
    #pragma unroll
    for (int o = 16; o > 0; o >>= 1) v += __shfl_down_sync(0xffffffffu, v, o);
    if (lane == 0) sbuf[wid] = v;
    __syncthreads();
    int nw = (blockDim.x + 31) >> 5;
    v = (threadIdx.x < nw) ? sbuf[threadIdx.x] : 0.f;
    if (wid == 0) {
        #pragma unroll
        for (int o = 16; o > 0; o >>= 1) v += __shfl_down_sync(0xffffffffu, v, o);
    }
    return v;  // valid on thread 0
}

// ---------------- prep: repack feat into pair-interleaved float2 ----------------
__global__ void k_prep(const float* __restrict__ feat) {
    int idx = blockIdx.x * 256 + threadIdx.x;
    if (idx >= NE*NPAIR*HW) return;
    int p = idx / HW, q = idx - p*HW;          // p = global pair = e*256 + pr
    const float* src = feat + (size_t)(p*2)*HW + q;
    g_feat2[idx] = make_float2(src[0], src[HW]);
}

// ---------------- init: copy weights, build label, zero accumulators ----------------
__global__ void k_init(const float* __restrict__ w_in, const float* __restrict__ bb) {
    int idx = blockIdx.x * 256 + threadIdx.x;
    if (idx < WSZ) g_w[idx] = w_in[idx];
    if (idx < NE*NPIX) {
        int e = idx / NPIX, p = idx - e*NPIX;
        int y = p / OH, x = p - y*OH;
        const float* b = bb + e*4;
        float cc = (b[0] + 0.5f*b[2]) * 0.0625f;   // col center
        float cr = (b[1] + 0.5f*b[3]) * 0.0625f;   // row center
        float dy = (float)y - cr, dx = (float)x - cc;
        g_label[idx] = expf(-0.5f*dy*dy) * expf(-0.5f*dx*dx);
    }
    if (blockIdx.x == 0 && threadIdx.x < 8) {
        g_loss_data[threadIdx.x] = 0.f;
        g_wsq[threadIdx.x] = 0.f;
    }
    if (blockIdx.x == 1 && threadIdx.x < NS) {
        g_alpha_num[0][threadIdx.x] = 0.f;
        g_alpha_num[1][threadIdx.x] = 0.f;
        g_alpha_den[0][threadIdx.x] = 0.f;
        g_alpha_den[1][threadIdx.x] = 0.f;
    }
}

// ---------------- conv: one (e, 32-channel chunk) per block, cp.async double-buffered ----------------
// 96 threads = 24 output tiles (4x across, 6y down; tile 6w x 4t) x 4 pair-lanes. (R4-proven)
__global__ __launch_bounds__(96, 4) void k_conv(int use_wg) {
    __shared__ __align__(16) float2 sf[2][SPP*SROW*SST]; // 2 x 4 pairs x 26x28 = 46.6KB
    __shared__ float2 swt[16][TAPS];                     // 16 pairs x 16 taps
    const float* wts = use_wg ? g_wg : g_w;

    int b = blockIdx.x;
    int e = b % NE;              // i*NS + s
    int chunk = b / NE;          // 0..15
    int s = e % NS;
    int tid = threadIdx.x;
    int pl = tid & 3;            // pair lane within stage
    int t  = tid >> 2;           // tile 0..23
    int tx = t & 3, ty = t >> 2;
    int x0 = tx * 6, y0 = ty * 4;
    int sulim = (ty == 5) ? 6 : 7;   // skip dead row read at bottom tile

    for (int k = tid; k < 2*SPP*SROW*SST; k += 96)
        ((float2*)sf)[k] = make_float2(0.f, 0.f);
    for (int k = tid; k < 256; k += 96) {
        int pr = k >> 4, tap = k & 15;
        const float* wp = wts + (s*NC + chunk*32 + pr*2)*TAPS + tap;
        swt[pr][tap] = make_float2(wp[0], wp[TAPS]);
    }
    __syncthreads();

    const float2* fbase = g_feat2 + (size_t)(e*NPAIR + chunk*16)*HW;
    unsigned long long pol = mkpol_evict_last();

    auto load_stage = [&](int st, float2* dstb) {
        for (int k = tid; k < 968; k += 96) {
            int p = k / 242, rem = k - p*242;
            int u = rem / 11, cc = rem - u*11;
            float2* dst = dstb + p*(SROW*SST) + (u+2)*SST + 2 + cc*2;
            const float2* src = fbase + (st*SPP + p)*HW + u*HH + cc*2;
            cpa16p(dst, src, pol);
        }
        cpa_commit();
    };

    float2 acc[4][6];
    #pragma unroll
    for (int r = 0; r < 4; r++)
        #pragma unroll
        for (int j = 0; j < 6; j++) acc[r][j] = make_float2(0.f, 0.f);

    load_stage(0, sf[0]);

    #pragma unroll 1
    for (int st = 0; st < 4; st++) {
        if (st < 3) { load_stage(st+1, sf[(st+1)&1]); cpa_wait<1>(); }
        else        { cpa_wait<0>(); }
        __syncthreads();

        const float2* sfp = sf[st&1] + pl*(SROW*SST);
        float2 wr[16];
        #pragma unroll
        for (int k = 0; k < 16; k++) wr[k] = swt[st*SPP + pl][k];

        #pragma unroll
        for (int su = 0; su < 7; su++) {
            if (su >= sulim) continue;
            const float2* fr = sfp + (y0+su)*SST + x0;
            float2 f[9];
            #pragma unroll
            for (int j = 0; j < 9; j++) f[j] = fr[j];
            #pragma unroll
            for (int ky = 0; ky < 4; ky++) {
                int r = su - ky;
                if (r < 0 || r > 3) continue;
                #pragma unroll
                for (int kx = 0; kx < 4; kx++) {
                    float2 w2 = wr[ky*4 + kx];
                    #pragma unroll
                    for (int j = 0; j < 6; j++)
                        acc[r][j] = f2fma(f[j+kx], w2, acc[r][j]);
                }
            }
        }
        __syncthreads();
    }

    float* op = g_spart + ((size_t)chunk*NE + e)*NPIX;
    #pragma unroll
    for (int r = 0; r < 4; r++) {
        #pragma unroll
        for (int j = 0; j < 6; j++) {
            float v = acc[r][j].x + acc[r][j].y;
            v += __shfl_down_sync(0xffffffffu, v, 1);
            v += __shfl_down_sync(0xffffffffu, v, 2);
            if (pl == 0) {
                int yy = y0 + r, xx = x0 + j;
                if (yy < OH && xx < OH) op[yy*OH + xx] = v;
            }
        }
    }
}

// ---------------- resid0: sum conv partials -> scores_0, rm_0, loss_data[0] ----------------
__global__ void k_resid0() {
    __shared__ float sred[32];
    int idx = blockIdx.x * 256 + threadIdx.x;
    float term = 0.f;
    if (idx < NE*NPIX) {
        float ssum = 0.f;
        #pragma unroll
        for (int ch = 0; ch < CSPLIT; ch++) ssum += g_spart[ch*(NE*NPIX) + idx];
        g_scores[idx] = ssum;
        float d = ssum - g_label[idx];
        g_rm[idx] = d * (1.f/3.f);
        term = d * d * (1.f/3.f);
    }
    float tot = block_reduce_sum(term, sred);
    if (threadIdx.x == 0) atomicAdd(&g_loss_data[0], tot);
}

// ---------------- grad: per-image partial of corr(feat, rm) ----------------
// Split 2x finer: block = (i, s, 16-channel group = 8 pairs), 2 stages of 4 pairs.
// Grid 3072 -> ~3 full waves (tail idle ~1% vs 25% at 1536).
__global__ __launch_bounds__(128, 7) void k_grad() {
    __shared__ __align__(16) float2 gf[4*HH*GFW];       // 16.9KB
    __shared__ float srm[PH*PH];
    float* scr = (float*)gf;                            // 128x33 scratch alias

    int b = blockIdx.x;
    int i = b / (NS*32);
    int rem = b - i*(NS*32);
    int s = rem >> 5;
    int cg = rem & 31;           // 16-channel group (8 pairs)
    int tid = threadIdx.x;
    int lane = tid & 31;
    int vseg = tid & 3;
    int uq   = (tid >> 2) & 7;
    int pr   = tid >> 5;
    int v0 = vseg * 6;
    int u0   = (uq < 6) ? uq*3 : 18 + (uq-6)*2;
    int ulen = (uq < 6) ? 3 : 2;

    for (int k = tid; k < 4*HH*GFW; k += 128) gf[k] = make_float2(0.f, 0.f);
    for (int k = tid; k < PH*PH; k += 128) srm[k] = 0.f;
    __syncthreads();
    for (int k = tid; k < NPIX; k += 128) {
        int y = k / OH, x = k - y*OH;
        srm[(y+2)*PH + (x+2)] = g_rm[(i*NS + s)*NPIX + k];
    }

    const float2* fbase = g_feat2 + (size_t)((i*NS + s)*NPAIR + cg*8)*HW;
    unsigned long long pol = mkpol_evict_last();

    #pragma unroll 1
    for (int st = 0; st < 2; st++) {
        __syncthreads();
        // feat stage load: 4 pairs x 22 rows x 11 x 16B via cp.async (evict_last)
        for (int k = tid; k < 968; k += 128) {
            int p = k / 242, r2 = k - p*242;
            int u = r2 / 11, cc = r2 - u*11;
            const float2* src = fbase + (st*4 + p)*HW + u*HH + cc*2;
            float2* dst = gf + p*(HH*GFW) + u*GFW + cc*2;
            cpa16p(dst, src, pol);
        }
        // re-zero right-pad cols (scratch reduction dirtied them last stage)
        for (int k = tid; k < 176; k += 128) {
            int p = k / 44, r2 = k - p*44;
            int u = r2 >> 1, c = HH + (r2 & 1);
            gf[p*(HH*GFW) + u*GFW + c] = make_float2(0.f, 0.f);
        }
        cpa_commit();
        cpa_wait<0>();
        __syncthreads();

        float2 acc[16];
        #pragma unroll
        for (int k = 0; k < 16; k++) acc[k] = make_float2(0.f, 0.f);

        const float2* fch = gf + pr*(HH*GFW);
        #pragma unroll 1
        for (int uu = 0; uu < ulen; uu++) {
            int u = u0 + uu;
            const float* r0p = srm + (u+4)*PH + v0;
            const float* r1p = r0p - PH;
            const float* r2p = r1p - PH;
            const float* r3p = r2p - PH;
            float w00=r0p[1], w01=r0p[2], w02=r0p[3];
            float w10=r1p[1], w11=r1p[2], w12=r1p[3];
            float w20=r2p[1], w21=r2p[2], w22=r2p[3];
            float w30=r3p[1], w31=r3p[2], w32=r3p[3];
            const float2* fr = fch + u*GFW + v0;
            #pragma unroll
            for (int v = 0; v < 6; v++) {
                float2 f = fr[v];
                float rn0 = r0p[v+4];
                acc[3]  = f2fma(f, fdup(w00), acc[3]);
                acc[2]  = f2fma(f, fdup(w01), acc[2]);
                acc[1]  = f2fma(f, fdup(w02), acc[1]);
                acc[0]  = f2fma(f, fdup(rn0), acc[0]);
                w00=w01; w01=w02; w02=rn0;
                float rn1 = r1p[v+4];
                acc[7]  = f2fma(f, fdup(w10), acc[7]);
                acc[6]  = f2fma(f, fdup(w11), acc[6]);
                acc[5]  = f2fma(f, fdup(w12), acc[5]);
                acc[4]  = f2fma(f, fdup(rn1), acc[4]);
                w10=w11; w11=w12; w12=rn1;
                float rn2 = r2p[v+4];
                acc[11] = f2fma(f, fdup(w20), acc[11]);
                acc[10] = f2fma(f, fdup(w21), acc[10]);
                acc[9]  = f2fma(f, fdup(w22), acc[9]);
                acc[8]  = f2fma(f, fdup(rn2), acc[8]);
                w20=w21; w21=w22; w22=rn2;
                float rn3 = r3p[v+4];
                acc[15] = f2fma(f, fdup(w30), acc[15]);
                acc[14] = f2fma(f, fdup(w31), acc[14]);
                acc[13] = f2fma(f, fdup(w32), acc[13]);
                acc[12] = f2fma(f, fdup(rn3), acc[12]);
                w30=w31; w31=w32; w32=rn3;
            }
        }

        __syncthreads();
        #pragma unroll
        for (int k = 0; k < 16; k++) {
            scr[(pr*32 + k)*33 + lane]      = acc[k].x;
            scr[(pr*32 + 16 + k)*33 + lane] = acc[k].y;
        }
        __syncthreads();
        {
            float sum = 0.f;
            #pragma unroll
            for (int p = 0; p < 32; p++) sum += scr[tid*33 + p];
            int pro = tid >> 5, half = (tid >> 4) & 1, tap = tid & 15;
            int c = cg*16 + (st*4 + pro)*2 + half;
            g_wgpart[(size_t)i*WSZ + (s*NC + c)*TAPS + tap] = sum;
        }
    }
}

// ---------------- combine grad partials: wg = sum_i part + reg*w; alpha_num; wsq ----------------
__global__ void k_comb(const float* __restrict__ freg, int t) {
    __shared__ float sred[32];
    int idx = blockIdx.x * 256 + threadIdx.x;   // grid covers exactly WSZ
    int s = idx >> 13;                          // / 8192
    float fr0 = freg[0];
    float regv = fmaxf(fr0*fr0, 1e-6f);
    float w = g_w[idx];
    float wg = g_wgpart[idx] + g_wgpart[WSZ + idx] + g_wgpart[2*WSZ + idx] + regv*w;
    g_wg[idx] = wg;
    float tn = block_reduce_sum(wg*wg, sred);
    if (threadIdx.x == 0) atomicAdd(&g_alpha_num[t&1][s], tn);
    __syncthreads();
    float tw = block_reduce_sum(w*w, sred);
    if (threadIdx.x == 0) atomicAdd(&g_wsq[t], tw);
}

// ---------------- alpha_den: (1/3)*sum conv(feat,wg)^2 ; also materialize g_sg ----------------
__global__ void k_den(int t) {
    __shared__ float sred[32];
    int e = blockIdx.x;
    int s = e % NS;
    float sum = 0.f;
    for (int p = threadIdx.x; p < NPIX; p += 256) {
        float v = 0.f;
        #pragma unroll
        for (int ch = 0; ch < CSPLIT; ch++) v += g_spart[ch*(NE*NPIX) + e*NPIX + p];
        g_sg[e*NPIX + p] = v;
        sum += v*v;
    }
    float tot = block_reduce_sum(sum, sred);
    if (threadIdx.x == 0) atomicAdd(&g_alpha_den[t&1][s], tot * (1.f/3.f));
}

// ---------------- merged update: weights, scores, rm_{t+1}, loss_data[t+1], zero next alphas ----------------
__global__ void k_upd(const float* __restrict__ lsl, const float* __restrict__ freg, int t) {
    __shared__ float sred[32];
    int idx = blockIdx.x * 256 + threadIdx.x;
    float fr0 = freg[0];
    float regv = fmaxf(fr0*fr0, 1e-6f);
    float step = expf(lsl[0]);
    int par = t & 1;
    if (idx < WSZ) {
        int s = idx >> 13;
        float num = g_alpha_num[par][s];
        float den = fmaxf(g_alpha_den[par][s] + regv*num, 1e-8f);
        g_w[idx] -= step * (num/den) * g_wg[idx];
        if (blockIdx.x == 0 && threadIdx.x < NS) {   // zero next-iteration slot
            g_alpha_num[par^1][threadIdx.x] = 0.f;
            g_alpha_den[par^1][threadIdx.x] = 0.f;
        }
    } else {
        int j = idx - WSZ;
        float term = 0.f;
        if (j < NE*NPIX) {
            int s = (j / NPIX) % NS;
            float num = g_alpha_num[par][s];
            float den = fmaxf(g_alpha_den[par][s] + regv*num, 1e-8f);
            float sc = g_scores[j] - step * (num/den) * g_sg[j];
            g_scores[j] = sc;
            float d = sc - g_label[j];
            g_rm[j] = d * (1.f/3.f);
            term = d * d * (1.f/3.f);
        }
        float tot = block_reduce_sum(term, sred);
        if (threadIdx.x == 0) atomicAdd(&g_loss_data[t+1], tot);
    }
}

// ---------------- final: weight writeback + wsq[5] (loss_data[5] from last k_upd) ----------------
__global__ void k_final(float* __restrict__ out) {
    __shared__ float sred[32];
    int j = blockIdx.x * 256 + threadIdx.x;   // grid covers exactly WSZ
    float wv = g_w[j];
    out[j] = wv;
    float tot = block_reduce_sum(wv*wv, sred);
    if (threadIdx.x == 0) atomicAdd(&g_wsq[5], tot);
}

// ---------------- losses writeback ----------------
__global__ void k_last(float* __restrict__ out, const float* __restrict__ freg) {
    float fr0 = freg[0];
    float regv = fmaxf(fr0*fr0, 1e-6f);
    int t = threadIdx.x;
    if (t < 6) out[WSZ + t] = (g_loss_data[t] + regv * g_wsq[t]) * (1.f/(float)NS);
}

// ---------------- launcher ----------------
extern "C" void kernel_launch(void* const* d_in, const int* in_sizes, int n_in,
                              void* d_out, int out_size) {
    const float* w_in = (const float*)d_in[0];
    const float* feat = (const float*)d_in[1];
    const float* bb   = (const float*)d_in[2];
    const float* lsl  = (const float*)d_in[3];
    const float* freg = (const float*)d_in[4];
    float* out = (float*)d_out;
    (void)in_sizes; (void)n_in; (void)out_size;

    k_init<<<1024, 256>>>(w_in, bb);
    k_prep<<<(NE*NPAIR*HW + 255)/256, 256>>>(feat);
    k_conv<<<NE*CSPLIT, 96>>>(0);                           // scores_0 partials
    k_resid0<<<(NE*NPIX + 255)/256, 256>>>();               // scores_0, rm_0, loss_data[0]
    for (int t = 0; t < 5; t++) {
        k_grad<<<NI*NS*32, 128>>>();                        // per-image grad partials (fine split)
        k_comb<<<WSZ/256, 256>>>(freg, t);                  // wg, alpha_num, wsq[t]
        k_conv<<<NE*CSPLIT, 96>>>(1);                       // sg partials from wg
        k_den<<<NE, 256>>>(t);                              // alpha_den + g_sg
        k_upd<<<(WSZ + NE*NPIX + 255)/256, 256>>>(lsl, freg, t); // w/scores/rm/loss
    }
    k_final<<<WSZ/256, 256>>>(out);                         // weights out + wsq[5]
    k_last<<<1, 32>>>(out, freg);                           // losses out
}

// round 16
// speedup vs baseline: 1.2684x; 1.0232x over previous
#include <cuda_runtime.h>
#include <math.h>

#define NI   3
#define NS   32
#define NC   512
#define HH   22
#define OH   23
#define NPIX (OH*OH)        // 529
#define HW   (HH*HH)        // 484
#define NE   (NI*NS)        // 96
#define TAPS 16
#define WSZ  (NS*NC*TAPS)   // 262144
#define CSPLIT 16
#define PH   27             // padded rm tile stride
#define SPP  2              // channel-pairs per conv stage
#define NSTG 8              // conv stages (8 x 2 pairs = 16)
#define SROW 26             // conv smem tile rows
#define SST  28             // conv smem tile row stride (float2)
#define GFW  24             // grad feat smem row stride (float2): 22 + 2 zero pad
#define NPAIR (NC/2)        // 256 pairs per element

// ---------------- scratch (device globals; no runtime allocation) ----------------
__device__ __align__(16) float2 g_feat2[NE*NPAIR*HW];  // pair-interleaved feat (95MB)
__device__ float g_spart[CSPLIT*NE*NPIX]; // conv partials per channel-chunk
__device__ float g_label[NE*NPIX];
__device__ float g_scores[NE*NPIX];       // maintained scores (recurrence)
__device__ float g_sg[NE*NPIX];           // conv(feat, wg) summed
__device__ float g_rm[NE*NPIX];           // residuals_mapped
__device__ float g_w[WSZ];                // working weights
__device__ float g_wg[WSZ];               // weights_grad
__device__ float g_wgpart[NI*WSZ];        // per-image grad partials
__device__ float g_alpha_num[2][NS];      // parity double-buffered
__device__ float g_alpha_den[2][NS];
__device__ float g_loss_data[8];
__device__ float g_wsq[8];

// ---------------- helpers ----------------
__device__ __forceinline__ float2 f2fma(float2 a, float2 b, float2 c) {
    float2 d;
    asm("fma.rn.f32x2 %0, %1, %2, %3;"
        : "=l"(reinterpret_cast<unsigned long long&>(d))
        : "l"(reinterpret_cast<unsigned long long&>(a)),
          "l"(reinterpret_cast<unsigned long long&>(b)),
          "l"(reinterpret_cast<unsigned long long&>(c)));
    return d;
}
__device__ __forceinline__ float2 fdup(float v) { return make_float2(v, v); }

__device__ __forceinline__ unsigned long long mkpol_evict_last() {
    unsigned long long pol;
    asm("createpolicy.fractional.L2::evict_last.b64 %0, 1.0;" : "=l"(pol));
    return pol;
}
__device__ __forceinline__ void cpa16p(void* dst, const void* src, unsigned long long pol) {
    unsigned int d = (unsigned int)__cvta_generic_to_shared(dst);
    asm volatile("cp.async.cg.shared.global.L2::cache_hint [%0], [%1], 16, %2;"
                 :: "r"(d), "l"(src), "l"(pol));
}
__device__ __forceinline__ void cpa_commit() { asm volatile("cp.async.commit_group;"); }
template<int N> __device__ __forceinline__ void cpa_wait() {
    asm volatile("cp.async.wait_group %0;" :: "n"(N));
}

__device__ __forceinline__ float block_reduce_sum(float v, float* sbuf) {
    int lane = threadIdx.x & 31, wid = threadIdx.x >> 5;
    #pragma unroll
    for (int o = 16; o > 0; o >>= 1) v += __shfl_down_sync(0xffffffffu, v, o);
    if (lane == 0) sbuf[wid] = v;
    __syncthreads();
    int nw = (blockDim.x + 31) >> 5;
    v = (threadIdx.x < nw) ? sbuf[threadIdx.x] : 0.f;
    if (wid == 0) {
        #pragma unroll
        for (int o = 16; o > 0; o >>= 1) v += __shfl_down_sync(0xffffffffu, v, o);
    }
    return v;  // valid on thread 0
}

// ---------------- prep: repack feat into pair-interleaved float2 ----------------
__global__ void k_prep(const float* __restrict__ feat) {
    int idx = blockIdx.x * 256 + threadIdx.x;
    if (idx >= NE*NPAIR*HW) return;
    int p = idx / HW, q = idx - p*HW;          // p = global pair = e*256 + pr
    const float* src = feat + (size_t)(p*2)*HW + q;
    g_feat2[idx] = make_float2(src[0], src[HW]);
}

// ---------------- init: copy weights, build label, zero accumulators ----------------
__global__ void k_init(const float* __restrict__ w_in, const float* __restrict__ bb) {
    int idx = blockIdx.x * 256 + threadIdx.x;
    if (idx < WSZ) g_w[idx] = w_in[idx];
    if (idx < NE*NPIX) {
        int e = idx / NPIX, p = idx - e*NPIX;
        int y = p / OH, x = p - y*OH;
        const float* b = bb + e*4;
        float cc = (b[0] + 0.5f*b[2]) * 0.0625f;   // col center
        float cr = (b[1] + 0.5f*b[3]) * 0.0625f;   // row center
        float dy = (float)y - cr, dx = (float)x - cc;
        g_label[idx] = expf(-0.5f*dy*dy) * expf(-0.5f*dx*dx);
    }
    if (blockIdx.x == 0 && threadIdx.x < 8) {
        g_loss_data[threadIdx.x] = 0.f;
        g_wsq[threadIdx.x] = 0.f;
    }
    if (blockIdx.x == 1 && threadIdx.x < NS) {
        g_alpha_num[0][threadIdx.x] = 0.f;
        g_alpha_num[1][threadIdx.x] = 0.f;
        g_alpha_den[0][threadIdx.x] = 0.f;
        g_alpha_den[1][threadIdx.x] = 0.f;
    }
}

// ---------------- conv: one (e, 32-channel chunk) per block, 3-deep cp.async ring ----------------
// 96 threads = 48 output tiles (8x across, 6y down; tile 3w x 4t) x 2 pair-lanes.
// 8 stages of 2 pairs; 3 smem buffers keep 2 stage-loads in flight; occupancy ~6.
__global__ __launch_bounds__(96, 4) void k_conv(int use_wg) {
    __shared__ __align__(16) float2 sf[3][SPP*SROW*SST]; // 3 x 2 pairs x 26x28 = 34.1KB
    __shared__ float2 swt[16][TAPS];                     // 16 pairs x 16 taps
    const float* wts = use_wg ? g_wg : g_w;

    int b = blockIdx.x;
    int e = b % NE;              // i*NS + s
    int chunk = b / NE;          // 0..15
    int s = e % NS;
    int tid = threadIdx.x;
    int pl = tid & 1;            // pair lane within stage
    int t  = tid >> 1;           // tile 0..47
    int tx = t & 7, ty = t >> 3;
    int x0 = tx * 3, y0 = ty * 4;
    int sulim = (ty == 5) ? 6 : 7;   // skip dead row read at bottom tile

    for (int k = tid; k < 3*SPP*SROW*SST; k += 96)
        ((float2*)sf)[k] = make_float2(0.f, 0.f);
    for (int k = tid; k < 256; k += 96) {
        int pr = k >> 4, tap = k & 15;
        const float* wp = wts + (s*NC + chunk*32 + pr*2)*TAPS + tap;
        swt[pr][tap] = make_float2(wp[0], wp[TAPS]);
    }
    __syncthreads();

    const float2* fbase = g_feat2 + (size_t)(e*NPAIR + chunk*16)*HW;
    unsigned long long pol = mkpol_evict_last();

    // stage loader: 2 pairs x 22 rows x 11 x 16B
    auto load_stage = [&](int st, float2* dstb) {
        for (int k = tid; k < 484; k += 96) {
            int p = k / 242, rem = k - p*242;
            int u = rem / 11, cc = rem - u*11;
            float2* dst = dstb + p*(SROW*SST) + (u+2)*SST + 2 + cc*2;
            const float2* src = fbase + (st*SPP + p)*HW + u*HH + cc*2;
            cpa16p(dst, src, pol);
        }
        cpa_commit();
    };

    float2 acc[4][3];
    #pragma unroll
    for (int r = 0; r < 4; r++)
        #pragma unroll
        for (int j = 0; j < 3; j++) acc[r][j] = make_float2(0.f, 0.f);

    load_stage(0, sf[0]);
    load_stage(1, sf[1]);

    #pragma unroll 1
    for (int st = 0; st < NSTG; st++) {
        if (st < NSTG-2) { load_stage(st+2, sf[(st+2)%3]); cpa_wait<2>(); }
        else if (st == NSTG-2) { cpa_wait<1>(); }
        else { cpa_wait<0>(); }
        __syncthreads();

        const float2* sfp = sf[st%3] + pl*(SROW*SST);
        float2 wr[16];
        #pragma unroll
        for (int k = 0; k < 16; k++) wr[k] = swt[st*SPP + pl][k];

        #pragma unroll
        for (int su = 0; su < 7; su++) {
            if (su >= sulim) continue;
            const float2* fr = sfp + (y0+su)*SST + x0;
            float2 f[6];
            #pragma unroll
            for (int j = 0; j < 6; j++) f[j] = fr[j];
            #pragma unroll
            for (int ky = 0; ky < 4; ky++) {
                int r = su - ky;
                if (r < 0 || r > 3) continue;
                #pragma unroll
                for (int kx = 0; kx < 4; kx++) {
                    float2 w2 = wr[ky*4 + kx];
                    #pragma unroll
                    for (int j = 0; j < 3; j++)
                        acc[r][j] = f2fma(f[j+kx], w2, acc[r][j]);
                }
            }
        }
        __syncthreads();   // buffer reuse fence
    }

    // sum 2 channels, reduce 2 pair-lanes via shfl
    float* op = g_spart + ((size_t)chunk*NE + e)*NPIX;
    #pragma unroll
    for (int r = 0; r < 4; r++) {
        #pragma unroll
        for (int j = 0; j < 3; j++) {
            float v = acc[r][j].x + acc[r][j].y;
            v += __shfl_down_sync(0xffffffffu, v, 1);
            if (pl == 0) {
                int yy = y0 + r, xx = x0 + j;
                if (yy < OH && xx < OH) op[yy*OH + xx] = v;
            }
        }
    }
}

// ---------------- resid0: sum conv partials -> scores_0, rm_0, loss_data[0] ----------------
__global__ void k_resid0() {
    __shared__ float sred[32];
    int idx = blockIdx.x * 256 + threadIdx.x;
    float term = 0.f;
    if (idx < NE*NPIX) {
        float ssum = 0.f;
        #pragma unroll
        for (int ch = 0; ch < CSPLIT; ch++) ssum += g_spart[ch*(NE*NPIX) + idx];
        g_scores[idx] = ssum;
        float d = ssum - g_label[idx];
        g_rm[idx] = d * (1.f/3.f);
        term = d * d * (1.f/3.f);
    }
    float tot = block_reduce_sum(term, sred);
    if (threadIdx.x == 0) atomicAdd(&g_loss_data[0], tot);
}

// ---------------- grad: per-image partial of corr(feat, rm) (R15-proven fine split) ----------------
__global__ __launch_bounds__(128, 7) void k_grad() {
    __shared__ __align__(16) float2 gf[4*HH*GFW];       // 16.9KB
    __shared__ float srm[PH*PH];
    float* scr = (float*)gf;                            // 128x33 scratch alias

    int b = blockIdx.x;
    int i = b / (NS*32);
    int rem = b - i*(NS*32);
    int s = rem >> 5;
    int cg = rem & 31;           // 16-channel group (8 pairs)
    int tid = threadIdx.x;
    int lane = tid & 31;
    int vseg = tid & 3;
    int uq   = (tid >> 2) & 7;
    int pr   = tid >> 5;
    int v0 = vseg * 6;
    int u0   = (uq < 6) ? uq*3 : 18 + (uq-6)*2;
    int ulen = (uq < 6) ? 3 : 2;

    for (int k = tid; k < 4*HH*GFW; k += 128) gf[k] = make_float2(0.f, 0.f);
    for (int k = tid; k < PH*PH; k += 128) srm[k] = 0.f;
    __syncthreads();
    for (int k = tid; k < NPIX; k += 128) {
        int y = k / OH, x = k - y*OH;
        srm[(y+2)*PH + (x+2)] = g_rm[(i*NS + s)*NPIX + k];
    }

    const float2* fbase = g_feat2 + (size_t)((i*NS + s)*NPAIR + cg*8)*HW;
    unsigned long long pol = mkpol_evict_last();

    #pragma unroll 1
    for (int st = 0; st < 2; st++) {
        __syncthreads();
        for (int k = tid; k < 968; k += 128) {
            int p = k / 242, r2 = k - p*242;
            int u = r2 / 11, cc = r2 - u*11;
            const float2* src = fbase + (st*4 + p)*HW + u*HH + cc*2;
            float2* dst = gf + p*(HH*GFW) + u*GFW + cc*2;
            cpa16p(dst, src, pol);
        }
        for (int k = tid; k < 176; k += 128) {
            int p = k / 44, r2 = k - p*44;
            int u = r2 >> 1, c = HH + (r2 & 1);
            gf[p*(HH*GFW) + u*GFW + c] = make_float2(0.f, 0.f);
        }
        cpa_commit();
        cpa_wait<0>();
        __syncthreads();

        float2 acc[16];
        #pragma unroll
        for (int k = 0; k < 16; k++) acc[k] = make_float2(0.f, 0.f);

        const float2* fch = gf + pr*(HH*GFW);
        #pragma unroll 1
        for (int uu = 0; uu < ulen; uu++) {
            int u = u0 + uu;
            const float* r0p = srm + (u+4)*PH + v0;
            const float* r1p = r0p - PH;
            const float* r2p = r1p - PH;
            const float* r3p = r2p - PH;
            float w00=r0p[1], w01=r0p[2], w02=r0p[3];
            float w10=r1p[1], w11=r1p[2], w12=r1p[3];
            float w20=r2p[1], w21=r2p[2], w22=r2p[3];
            float w30=r3p[1], w31=r3p[2], w32=r3p[3];
            const float2* fr = fch + u*GFW + v0;
            #pragma unroll
            for (int v = 0; v < 6; v++) {
                float2 f = fr[v];
                float rn0 = r0p[v+4];
                acc[3]  = f2fma(f, fdup(w00), acc[3]);
                acc[2]  = f2fma(f, fdup(w01), acc[2]);
                acc[1]  = f2fma(f, fdup(w02), acc[1]);
                acc[0]  = f2fma(f, fdup(rn0), acc[0]);
                w00=w01; w01=w02; w02=rn0;
                float rn1 = r1p[v+4];
                acc[7]  = f2fma(f, fdup(w10), acc[7]);
                acc[6]  = f2fma(f, fdup(w11), acc[6]);
                acc[5]  = f2fma(f, fdup(w12), acc[5]);
                acc[4]  = f2fma(f, fdup(rn1), acc[4]);
                w10=w11; w11=w12; w12=rn1;
                float rn2 = r2p[v+4];
                acc[11] = f2fma(f, fdup(w20), acc[11]);
                acc[10] = f2fma(f, fdup(w21), acc[10]);
                acc[9]  = f2fma(f, fdup(w22), acc[9]);
                acc[8]  = f2fma(f, fdup(rn2), acc[8]);
                w20=w21; w21=w22; w22=rn2;
                float rn3 = r3p[v+4];
                acc[15] = f2fma(f, fdup(w30), acc[15]);
                acc[14] = f2fma(f, fdup(w31), acc[14]);
                acc[13] = f2fma(f, fdup(w32), acc[13]);
                acc[12] = f2fma(f, fdup(rn3), acc[12]);
                w30=w31; w31=w32; w32=rn3;
            }
        }

        __syncthreads();
        #pragma unroll
        for (int k = 0; k < 16; k++) {
            scr[(pr*32 + k)*33 + lane]      = acc[k].x;
            scr[(pr*32 + 16 + k)*33 + lane] = acc[k].y;
        }
        __syncthreads();
        {
            float sum = 0.f;
            #pragma unroll
            for (int p = 0; p < 32; p++) sum += scr[tid*33 + p];
            int pro = tid >> 5, half = (tid >> 4) & 1, tap = tid & 15;
            int c = cg*16 + (st*4 + pro)*2 + half;
            g_wgpart[(size_t)i*WSZ + (s*NC + c)*TAPS + tap] = sum;
        }
    }
}

// ---------------- combine grad partials: wg = sum_i part + reg*w; alpha_num; wsq ----------------
__global__ void k_comb(const float* __restrict__ freg, int t) {
    __shared__ float sred[32];
    int idx = blockIdx.x * 256 + threadIdx.x;   // grid covers exactly WSZ
    int s = idx >> 13;                          // / 8192
    float fr0 = freg[0];
    float regv = fmaxf(fr0*fr0, 1e-6f);
    float w = g_w[idx];
    float wg = g_wgpart[idx] + g_wgpart[WSZ + idx] + g_wgpart[2*WSZ + idx] + regv*w;
    g_wg[idx] = wg;
    float tn = block_reduce_sum(wg*wg, sred);
    if (threadIdx.x == 0) atomicAdd(&g_alpha_num[t&1][s], tn);
    __syncthreads();
    float tw = block_reduce_sum(w*w, sred);
    if (threadIdx.x == 0) atomicAdd(&g_wsq[t], tw);
}

// ---------------- alpha_den: (1/3)*sum conv(feat,wg)^2 ; also materialize g_sg ----------------
__global__ void k_den(int t) {
    __shared__ float sred[32];
    int e = blockIdx.x;
    int s = e % NS;
    float sum = 0.f;
    for (int p = threadIdx.x; p < NPIX; p += 256) {
        float v = 0.f;
        #pragma unroll
        for (int ch = 0; ch < CSPLIT; ch++) v += g_spart[ch*(NE*NPIX) + e*NPIX + p];
        g_sg[e*NPIX + p] = v;
        sum += v*v;
    }
    float tot = block_reduce_sum(sum, sred);
    if (threadIdx.x == 0) atomicAdd(&g_alpha_den[t&1][s], tot * (1.f/3.f));
}

// ---------------- merged update: weights, scores, rm_{t+1}, loss_data[t+1], zero next alphas ----------------
__global__ void k_upd(const float* __restrict__ lsl, const float* __restrict__ freg, int t) {
    __shared__ float sred[32];
    int idx = blockIdx.x * 256 + threadIdx.x;
    float fr0 = freg[0];
    float regv = fmaxf(fr0*fr0, 1e-6f);
    float step = expf(lsl[0]);
    int par = t & 1;
    if (idx < WSZ) {
        int s = idx >> 13;
        float num = g_alpha_num[par][s];
        float den = fmaxf(g_alpha_den[par][s] + regv*num, 1e-8f);
        g_w[idx] -= step * (num/den) * g_wg[idx];
        if (blockIdx.x == 0 && threadIdx.x < NS) {   // zero next-iteration slot
            g_alpha_num[par^1][threadIdx.x] = 0.f;
            g_alpha_den[par^1][threadIdx.x] = 0.f;
        }
    } else {
        int j = idx - WSZ;
        float term = 0.f;
        if (j < NE*NPIX) {
            int s = (j / NPIX) % NS;
            float num = g_alpha_num[par][s];
            float den = fmaxf(g_alpha_den[par][s] + regv*num, 1e-8f);
            float sc = g_scores[j] - step * (num/den) * g_sg[j];
            g_scores[j] = sc;
            float d = sc - g_label[j];
            g_rm[j] = d * (1.f/3.f);
            term = d * d * (1.f/3.f);
        }
        float tot = block_reduce_sum(term, sred);
        if (threadIdx.x == 0) atomicAdd(&g_loss_data[t+1], tot);
    }
}

// ---------------- final: weight writeback + wsq[5] (loss_data[5] from last k_upd) ----------------
__global__ void k_final(float* __restrict__ out) {
    __shared__ float sred[32];
    int j = blockIdx.x * 256 + threadIdx.x;   // grid covers exactly WSZ
    float wv = g_w[j];
    out[j] = wv;
    float tot = block_reduce_sum(wv*wv, sred);
    if (threadIdx.x == 0) atomicAdd(&g_wsq[5], tot);
}

// ---------------- losses writeback ----------------
__global__ void k_last(float* __restrict__ out, const float* __restrict__ freg) {
    float fr0 = freg[0];
    float regv = fmaxf(fr0*fr0, 1e-6f);
    int t = threadIdx.x;
    if (t < 6) out[WSZ + t] = (g_loss_data[t] + regv * g_wsq[t]) * (1.f/(float)NS);
}

// ---------------- launcher ----------------
extern "C" void kernel_launch(void* const* d_in, const int* in_sizes, int n_in,
                              void* d_out, int out_size) {
    const float* w_in = (const float*)d_in[0];
    const float* feat = (const float*)d_in[1];
    const float* bb   = (const float*)d_in[2];
    const float* lsl  = (const float*)d_in[3];
    const float* freg = (const float*)d_in[4];
    float* out = (float*)d_out;
    (void)in_sizes; (void)n_in; (void)out_size;

    k_init<<<1024, 256>>>(w_in, bb);
    k_prep<<<(NE*NPAIR*HW + 255)/256, 256>>>(feat);
    k_conv<<<NE*CSPLIT, 96>>>(0);                           // scores_0 partials
    k_resid0<<<(NE*NPIX + 255)/256, 256>>>();               // scores_0, rm_0, loss_data[0]
    for (int t = 0; t < 5; t++) {
        k_grad<<<NI*NS*32, 128>>>();                        // per-image grad partials
        k_comb<<<WSZ/256, 256>>>(freg, t);                  // wg, alpha_num, wsq[t]
        k_conv<<<NE*CSPLIT, 96>>>(1);                       // sg partials from wg
        k_den<<<NE, 256>>>(t);                              // alpha_den + g_sg
        k_upd<<<(WSZ + NE*NPIX + 255)/256, 256>>>(lsl, freg, t); // w/scores/rm/loss
    }
    k_final<<<WSZ/256, 256>>>(out);                         // weights out + wsq[5]
    k_last<<<1, 32>>>(out, freg);                           // losses out
}

// round 17
// speedup vs baseline: 1.2922x; 1.0187x over previous
#include <cuda_runtime.h>
#include <math.h>

#define NI   3
#define NS   32
#define NC   512
#define HH   22
#define OH   23
#define NPIX (OH*OH)        // 529
#define HW   (HH*HH)        // 484
#define NE   (NI*NS)        // 96
#define TAPS 16
#define WSZ  (NS*NC*TAPS)   // 262144
#define CSPLIT 16
#define PH   27             // padded rm tile stride
#define SPP  2              // channel-pairs per conv stage
#define NSTG 8              // conv stages (8 x 2 pairs = 16)
#define SROW 26             // conv smem tile rows
#define SST  28             // conv smem tile row stride (float2)
#define GFW  24             // grad feat smem row stride (float2): 22 + 2 zero pad
#define NPAIR (NC/2)        // 256 pairs per element

// ---------------- scratch (device globals; no runtime allocation) ----------------
__device__ __align__(16) float2 g_feat2[NE*NPAIR*HW];  // pair-interleaved feat (95MB)
__device__ float g_spart[CSPLIT*NE*NPIX]; // conv partials per channel-chunk
__device__ float g_label[NE*NPIX];
__device__ float g_scores[NE*NPIX];       // maintained scores (recurrence)
__device__ float g_sg[NE*NPIX];           // conv(feat, wg) summed
__device__ float g_rm[NE*NPIX];           // residuals_mapped
__device__ float g_w[WSZ];                // working weights
__device__ float g_wgpart[NI*WSZ];        // per-image grad partials
__device__ float g_alpha_num[2][NS];      // parity double-buffered
__device__ float g_alpha_den[2][NS];
__device__ float g_loss_data[8];
__device__ float g_wsq[8];

// ---------------- helpers ----------------
__device__ __forceinline__ float2 f2fma(float2 a, float2 b, float2 c) {
    float2 d;
    asm("fma.rn.f32x2 %0, %1, %2, %3;"
        : "=l"(reinterpret_cast<unsigned long long&>(d))
        : "l"(reinterpret_cast<unsigned long long&>(a)),
          "l"(reinterpret_cast<unsigned long long&>(b)),
          "l"(reinterpret_cast<unsigned long long&>(c)));
    return d;
}
__device__ __forceinline__ float2 fdup(float v) { return make_float2(v, v); }

__device__ __forceinline__ unsigned long long mkpol_evict_last() {
    unsigned long long pol;
    asm("createpolicy.fractional.L2::evict_last.b64 %0, 1.0;" : "=l"(pol));
    return pol;
}
__device__ __forceinline__ void cpa16p(void* dst, const void* src, unsigned long long pol) {
    unsigned int d = (unsigned int)__cvta_generic_to_shared(dst);
    asm volatile("cp.async.cg.shared.global.L2::cache_hint [%0], [%1], 16, %2;"
                 :: "r"(d), "l"(src), "l"(pol));
}
__device__ __forceinline__ void cpa_commit() { asm volatile("cp.async.commit_group;"); }
template<int N> __device__ __forceinline__ void cpa_wait() {
    asm volatile("cp.async.wait_group %0;" :: "n"(N));
}

__device__ __forceinline__ float block_reduce_sum(float v, float* sbuf) {
    int lane = threadIdx.x & 31, wid = threadIdx.x >> 5;
    #pragma unroll
    for (int o = 16; o > 0; o >>= 1) v += __shfl_down_sync(0xffffffffu, v, o);
    if (lane == 0) sbuf[wid] = v;
    __syncthreads();
    int nw = (blockDim.x + 31) >> 5;
    v = (threadIdx.x < nw) ? sbuf[threadIdx.x] : 0.f;
    if (wid == 0) {
        #pragma unroll
        for (int o = 16; o > 0; o >>= 1) v += __shfl_down_sync(0xffffffffu, v, o);
    }
    return v;  // valid on thread 0
}

// ---------------- prep: repack feat into pair-interleaved float2 ----------------
__global__ void k_prep(const float* __restrict__ feat) {
    int idx = blockIdx.x * 256 + threadIdx.x;
    if (idx >= NE*NPAIR*HW) return;
    int p = idx / HW, q = idx - p*HW;          // p = global pair = e*256 + pr
    const float* src = feat + (size_t)(p*2)*HW + q;
    g_feat2[idx] = make_float2(src[0], src[HW]);
}

// ---------------- init: copy weights, build label, zero accumulators ----------------
__global__ void k_init(const float* __restrict__ w_in, const float* __restrict__ bb) {
    int idx = blockIdx.x * 256 + threadIdx.x;
    if (idx < WSZ) g_w[idx] = w_in[idx];
    if (idx < NE*NPIX) {
        int e = idx / NPIX, p = idx - e*NPIX;
        int y = p / OH, x = p - y*OH;
        const float* b = bb + e*4;
        float cc = (b[0] + 0.5f*b[2]) * 0.0625f;   // col center
        float cr = (b[1] + 0.5f*b[3]) * 0.0625f;   // row center
        float dy = (float)y - cr, dx = (float)x - cc;
        g_label[idx] = expf(-0.5f*dy*dy) * expf(-0.5f*dx*dx);
    }
    if (blockIdx.x == 0 && threadIdx.x < 8) {
        g_loss_data[threadIdx.x] = 0.f;
        g_wsq[threadIdx.x] = 0.f;
    }
    if (blockIdx.x == 1 && threadIdx.x < NS) {
        g_alpha_num[0][threadIdx.x] = 0.f;
        g_alpha_num[1][threadIdx.x] = 0.f;
        g_alpha_den[0][threadIdx.x] = 0.f;
        g_alpha_den[1][threadIdx.x] = 0.f;
    }
}

// ---------------- conv: one (e, 32-channel chunk) per block, 3-deep cp.async ring ----------------
// use_wg=1: weights = wg computed on the fly from wgpart + reg*w; i==0 blocks also
// fold alpha_num[s] (sum wg^2) and wsq[t] (sum w^2). k_comb eliminated.
__global__ __launch_bounds__(96, 4) void k_conv(int use_wg, const float* __restrict__ freg, int t) {
    __shared__ __align__(16) float2 sf[3][SPP*SROW*SST]; // 3 x 2 pairs x 26x28 = 34.1KB
    __shared__ float2 swt[16][TAPS];                     // 16 pairs x 16 taps
    __shared__ float sred[32];

    int b = blockIdx.x;
    int e = b % NE;              // i*NS + s
    int chunk = b / NE;          // 0..15
    int s = e % NS;
    int img = e / NS;            // 0..2
    int tid = threadIdx.x;
    int pl = tid & 1;            // pair lane within stage
    int t2  = tid >> 1;          // tile 0..47
    int tx = t2 & 7, ty = t2 >> 3;
    int x0 = tx * 3, y0 = ty * 4;
    int sulim = (ty == 5) ? 6 : 7;   // skip dead row read at bottom tile

    for (int k = tid; k < 3*SPP*SROW*SST; k += 96)
        ((float2*)sf)[k] = make_float2(0.f, 0.f);

    // weight staging; for use_wg: wg = sum_i wgpart + reg*w, with alpha_num/wsq side-sums
    float nacc = 0.f, wacc = 0.f;
    {
        float fr0 = freg[0];
        float regv = fmaxf(fr0*fr0, 1e-6f);
        for (int k = tid; k < 256; k += 96) {
            int pr = k >> 4, tap = k & 15;
            int base = (s*NC + chunk*32 + pr*2)*TAPS + tap;
            float wx = g_w[base], wy = g_w[base + TAPS];
            if (use_wg) {
                float gx = g_wgpart[base] + g_wgpart[WSZ + base] + g_wgpart[2*WSZ + base] + regv*wx;
                float gy = g_wgpart[base + TAPS] + g_wgpart[WSZ + base + TAPS]
                         + g_wgpart[2*WSZ + base + TAPS] + regv*wy;
                swt[pr][tap] = make_float2(gx, gy);
                nacc += gx*gx + gy*gy;
                wacc += wx*wx + wy*wy;
            } else {
                swt[pr][tap] = make_float2(wx, wy);
            }
        }
    }
    if (use_wg && img == 0) {
        float tn = block_reduce_sum(nacc, sred);
        if (tid == 0) atomicAdd(&g_alpha_num[t&1][s], tn);
        __syncthreads();
        float tw = block_reduce_sum(wacc, sred);
        if (tid == 0) atomicAdd(&g_wsq[t], tw);
    }
    __syncthreads();

    const float2* fbase = g_feat2 + (size_t)(e*NPAIR + chunk*16)*HW;
    unsigned long long pol = mkpol_evict_last();

    // stage loader: 2 pairs x 22 rows x 11 x 16B
    auto load_stage = [&](int st, float2* dstb) {
        for (int k = tid; k < 484; k += 96) {
            int p = k / 242, rem = k - p*242;
            int u = rem / 11, cc = rem - u*11;
            float2* dst = dstb + p*(SROW*SST) + (u+2)*SST + 2 + cc*2;
            const float2* src = fbase + (st*SPP + p)*HW + u*HH + cc*2;
            cpa16p(dst, src, pol);
        }
        cpa_commit();
    };

    float2 acc[4][3];
    #pragma unroll
    for (int r = 0; r < 4; r++)
        #pragma unroll
        for (int j = 0; j < 3; j++) acc[r][j] = make_float2(0.f, 0.f);

    load_stage(0, sf[0]);
    load_stage(1, sf[1]);

    #pragma unroll 1
    for (int st = 0; st < NSTG; st++) {
        if (st < NSTG-2) { load_stage(st+2, sf[(st+2)%3]); cpa_wait<2>(); }
        else if (st == NSTG-2) { cpa_wait<1>(); }
        else { cpa_wait<0>(); }
        __syncthreads();

        const float2* sfp = sf[st%3] + pl*(SROW*SST);
        float2 wr[16];
        #pragma unroll
        for (int k = 0; k < 16; k++) wr[k] = swt[st*SPP + pl][k];

        #pragma unroll
        for (int su = 0; su < 7; su++) {
            if (su >= sulim) continue;
            const float2* fr = sfp + (y0+su)*SST + x0;
            float2 f[6];
            #pragma unroll
            for (int j = 0; j < 6; j++) f[j] = fr[j];
            #pragma unroll
            for (int ky = 0; ky < 4; ky++) {
                int r = su - ky;
                if (r < 0 || r > 3) continue;
                #pragma unroll
                for (int kx = 0; kx < 4; kx++) {
                    float2 w2 = wr[ky*4 + kx];
                    #pragma unroll
                    for (int j = 0; j < 3; j++)
                        acc[r][j] = f2fma(f[j+kx], w2, acc[r][j]);
                }
            }
        }
        __syncthreads();   // buffer reuse fence
    }

    // sum 2 channels, reduce 2 pair-lanes via shfl
    float* op = g_spart + ((size_t)chunk*NE + e)*NPIX;
    #pragma unroll
    for (int r = 0; r < 4; r++) {
        #pragma unroll
        for (int j = 0; j < 3; j++) {
            float v = acc[r][j].x + acc[r][j].y;
            v += __shfl_down_sync(0xffffffffu, v, 1);
            if (pl == 0) {
                int yy = y0 + r, xx = x0 + j;
                if (yy < OH && xx < OH) op[yy*OH + xx] = v;
            }
        }
    }
}

// ---------------- resid0: sum conv partials -> scores_0, rm_0, loss_data[0] ----------------
__global__ void k_resid0() {
    __shared__ float sred[32];
    int idx = blockIdx.x * 256 + threadIdx.x;
    float term = 0.f;
    if (idx < NE*NPIX) {
        float ssum = 0.f;
        #pragma unroll
        for (int ch = 0; ch < CSPLIT; ch++) ssum += g_spart[ch*(NE*NPIX) + idx];
        g_scores[idx] = ssum;
        float d = ssum - g_label[idx];
        g_rm[idx] = d * (1.f/3.f);
        term = d * d * (1.f/3.f);
    }
    float tot = block_reduce_sum(term, sred);
    if (threadIdx.x == 0) atomicAdd(&g_loss_data[0], tot);
}

// ---------------- grad: per-image partial of corr(feat, rm) (R15-proven fine split) ----------------
__global__ __launch_bounds__(128, 7) void k_grad() {
    __shared__ __align__(16) float2 gf[4*HH*GFW];       // 16.9KB
    __shared__ float srm[PH*PH];
    float* scr = (float*)gf;                            // 128x33 scratch alias

    int b = blockIdx.x;
    int i = b / (NS*32);
    int rem = b - i*(NS*32);
    int s = rem >> 5;
    int cg = rem & 31;           // 16-channel group (8 pairs)
    int tid = threadIdx.x;
    int lane = tid & 31;
    int vseg = tid & 3;
    int uq   = (tid >> 2) & 7;
    int pr   = tid >> 5;
    int v0 = vseg * 6;
    int u0   = (uq < 6) ? uq*3 : 18 + (uq-6)*2;
    int ulen = (uq < 6) ? 3 : 2;

    for (int k = tid; k < 4*HH*GFW; k += 128) gf[k] = make_float2(0.f, 0.f);
    for (int k = tid; k < PH*PH; k += 128) srm[k] = 0.f;
    __syncthreads();
    for (int k = tid; k < NPIX; k += 128) {
        int y = k / OH, x = k - y*OH;
        srm[(y+2)*PH + (x+2)] = g_rm[(i*NS + s)*NPIX + k];
    }

    const float2* fbase = g_feat2 + (size_t)((i*NS + s)*NPAIR + cg*8)*HW;
    unsigned long long pol = mkpol_evict_last();

    #pragma unroll 1
    for (int st = 0; st < 2; st++) {
        __syncthreads();
        for (int k = tid; k < 968; k += 128) {
            int p = k / 242, r2 = k - p*242;
            int u = r2 / 11, cc = r2 - u*11;
            const float2* src = fbase + (st*4 + p)*HW + u*HH + cc*2;
            float2* dst = gf + p*(HH*GFW) + u*GFW + cc*2;
            cpa16p(dst, src, pol);
        }
        for (int k = tid; k < 176; k += 128) {
            int p = k / 44, r2 = k - p*44;
            int u = r2 >> 1, c = HH + (r2 & 1);
            gf[p*(HH*GFW) + u*GFW + c] = make_float2(0.f, 0.f);
        }
        cpa_commit();
        cpa_wait<0>();
        __syncthreads();

        float2 acc[16];
        #pragma unroll
        for (int k = 0; k < 16; k++) acc[k] = make_float2(0.f, 0.f);

        const float2* fch = gf + pr*(HH*GFW);
        #pragma unroll 1
        for (int uu = 0; uu < ulen; uu++) {
            int u = u0 + uu;
            const float* r0p = srm + (u+4)*PH + v0;
            const float* r1p = r0p - PH;
            const float* r2p = r1p - PH;
            const float* r3p = r2p - PH;
            float w00=r0p[1], w01=r0p[2], w02=r0p[3];
            float w10=r1p[1], w11=r1p[2], w12=r1p[3];
            float w20=r2p[1], w21=r2p[2], w22=r2p[3];
            float w30=r3p[1], w31=r3p[2], w32=r3p[3];
            const float2* fr = fch + u*GFW + v0;
            #pragma unroll
            for (int v = 0; v < 6; v++) {
                float2 f = fr[v];
                float rn0 = r0p[v+4];
                acc[3]  = f2fma(f, fdup(w00), acc[3]);
                acc[2]  = f2fma(f, fdup(w01), acc[2]);
                acc[1]  = f2fma(f, fdup(w02), acc[1]);
                acc[0]  = f2fma(f, fdup(rn0), acc[0]);
                w00=w01; w01=w02; w02=rn0;
                float rn1 = r1p[v+4];
                acc[7]  = f2fma(f, fdup(w10), acc[7]);
                acc[6]  = f2fma(f, fdup(w11), acc[6]);
                acc[5]  = f2fma(f, fdup(w12), acc[5]);
                acc[4]  = f2fma(f, fdup(rn1), acc[4]);
                w10=w11; w11=w12; w12=rn1;
                float rn2 = r2p[v+4];
                acc[11] = f2fma(f, fdup(w20), acc[11]);
                acc[10] = f2fma(f, fdup(w21), acc[10]);
                acc[9]  = f2fma(f, fdup(w22), acc[9]);
                acc[8]  = f2fma(f, fdup(rn2), acc[8]);
                w20=w21; w21=w22; w22=rn2;
                float rn3 = r3p[v+4];
                acc[15] = f2fma(f, fdup(w30), acc[15]);
                acc[14] = f2fma(f, fdup(w31), acc[14]);
                acc[13] = f2fma(f, fdup(w32), acc[13]);
                acc[12] = f2fma(f, fdup(rn3), acc[12]);
                w30=w31; w31=w32; w32=rn3;
            }
        }

        __syncthreads();
        #pragma unroll
        for (int k = 0; k < 16; k++) {
            scr[(pr*32 + k)*33 + lane]      = acc[k].x;
            scr[(pr*32 + 16 + k)*33 + lane] = acc[k].y;
        }
        __syncthreads();
        {
            float sum = 0.f;
            #pragma unroll
            for (int p = 0; p < 32; p++) sum += scr[tid*33 + p];
            int pro = tid >> 5, half = (tid >> 4) & 1, tap = tid & 15;
            int c = cg*16 + (st*4 + pro)*2 + half;
            g_wgpart[(size_t)i*WSZ + (s*NC + c)*TAPS + tap] = sum;
        }
    }
}

// ---------------- alpha_den: (1/3)*sum conv(feat,wg)^2 ; also materialize g_sg ----------------
__global__ void k_den(int t) {
    __shared__ float sred[32];
    int e = blockIdx.x;
    int s = e % NS;
    float sum = 0.f;
    for (int p = threadIdx.x; p < NPIX; p += 256) {
        float v = 0.f;
        #pragma unroll
        for (int ch = 0; ch < CSPLIT; ch++) v += g_spart[ch*(NE*NPIX) + e*NPIX + p];
        g_sg[e*NPIX + p] = v;
        sum += v*v;
    }
    float tot = block_reduce_sum(sum, sred);
    if (threadIdx.x == 0) atomicAdd(&g_alpha_den[t&1][s], tot * (1.f/3.f));
}

// ---------------- merged update: weights, scores, rm_{t+1}, loss_data[t+1], zero next alphas ----------------
// wg recomputed from wgpart + reg*w (g_wg eliminated).
__global__ void k_upd(const float* __restrict__ lsl, const float* __restrict__ freg, int t) {
    __shared__ float sred[32];
    int idx = blockIdx.x * 256 + threadIdx.x;
    float fr0 = freg[0];
    float regv = fmaxf(fr0*fr0, 1e-6f);
    float step = expf(lsl[0]);
    int par = t & 1;
    if (idx < WSZ) {
        int s = idx >> 13;
        float num = g_alpha_num[par][s];
        float den = fmaxf(g_alpha_den[par][s] + regv*num, 1e-8f);
        float w = g_w[idx];
        float wg = g_wgpart[idx] + g_wgpart[WSZ + idx] + g_wgpart[2*WSZ + idx] + regv*w;
        g_w[idx] = w - step * (num/den) * wg;
        if (blockIdx.x == 0 && threadIdx.x < NS) {   // zero next-iteration slot
            g_alpha_num[par^1][threadIdx.x] = 0.f;
            g_alpha_den[par^1][threadIdx.x] = 0.f;
        }
    } else {
        int j = idx - WSZ;
        float term = 0.f;
        if (j < NE*NPIX) {
            int s = (j / NPIX) % NS;
            float num = g_alpha_num[par][s];
            float den = fmaxf(g_alpha_den[par][s] + regv*num, 1e-8f);
            float sc = g_scores[j] - step * (num/den) * g_sg[j];
            g_scores[j] = sc;
            float d = sc - g_label[j];
            g_rm[j] = d * (1.f/3.f);
            term = d * d * (1.f/3.f);
        }
        float tot = block_reduce_sum(term, sred);
        if (threadIdx.x == 0) atomicAdd(&g_loss_data[t+1], tot);
    }
}

// ---------------- final: weight writeback + wsq[5] (loss_data[5] from last k_upd) ----------------
__global__ void k_final(float* __restrict__ out) {
    __shared__ float sred[32];
    int j = blockIdx.x * 256 + threadIdx.x;   // grid covers exactly WSZ
    float wv = g_w[j];
    out[j] = wv;
    float tot = block_reduce_sum(wv*wv, sred);
    if (threadIdx.x == 0) atomicAdd(&g_wsq[5], tot);
}

// ---------------- losses writeback ----------------
__global__ void k_last(float* __restrict__ out, const float* __restrict__ freg) {
    float fr0 = freg[0];
    float regv = fmaxf(fr0*fr0, 1e-6f);
    int t = threadIdx.x;
    if (t < 6) out[WSZ + t] = (g_loss_data[t] + regv * g_wsq[t]) * (1.f/(float)NS);
}

// ---------------- launcher ----------------
extern "C" void kernel_launch(void* const* d_in, const int* in_sizes, int n_in,
                              void* d_out, int out_size) {
    const float* w_in = (const float*)d_in[0];
    const float* feat = (const float*)d_in[1];
    const float* bb   = (const float*)d_in[2];
    const float* lsl  = (const float*)d_in[3];
    const float* freg = (const float*)d_in[4];
    float* out = (float*)d_out;
    (void)in_sizes; (void)n_in; (void)out_size;

    k_init<<<1024, 256>>>(w_in, bb);
    k_prep<<<(NE*NPAIR*HW + 255)/256, 256>>>(feat);
    k_conv<<<NE*CSPLIT, 96>>>(0, freg, 0);                  // scores_0 partials
    k_resid0<<<(NE*NPIX + 255)/256, 256>>>();               // scores_0, rm_0, loss_data[0]
    for (int t = 0; t < 5; t++) {
        k_grad<<<NI*NS*32, 128>>>();                        // per-image grad partials
        k_conv<<<NE*CSPLIT, 96>>>(1, freg, t);              // wg on-the-fly -> sg partials + alpha_num + wsq
        k_den<<<NE, 256>>>(t);                              // alpha_den + g_sg
        k_upd<<<(WSZ + NE*NPIX + 255)/256, 256>>>(lsl, freg, t); // w/scores/rm/loss
    }
    k_final<<<WSZ/256, 256>>>(out);                         // weights out + wsq[5]
    k_last<<<1, 32>>>(out, freg);                           // losses out
}